// round 7
// baseline (speedup 1.0000x reference)
#include <cuda_runtime.h>
#include <math.h>

#define NNODES 2048
#define NEDGES 32768

__constant__ float c_fact[16] = {
    1.f, 1.f, 2.f, 6.f, 24.f, 120.f, 720.f, 5040.f, 40320.f, 362880.f,
    3628800.f, 39916800.f, 479001600.f, 6227020800.f, 87178291200.f, 1307674368000.f};

struct DevConsts {
    float cg[576];
    float rec1[45];
    float rec2[105];
    float sh_s0, sh_s1, silu_c;
};
__device__ DevConsts g_c;

__device__ __align__(16) float g_node_sum[NNODES * 1024];
__device__ __align__(16) float g_W0T[8192];
__device__ __align__(16) float g_Wg1[20480];
__device__ __align__(16) float g_Wg2[20480];
__device__ __align__(16) float g_W1r[20480];
__device__ __align__(16) float g_vbuf[(size_t)8 * NEDGES * 320];
__device__ __align__(16) float g_x2buf[(size_t)NEDGES * 320];
__device__ __align__(16) float g_h1[(size_t)NEDGES * 64];

__device__ __forceinline__ float to_tf32(float x) {
    unsigned r;
    asm("cvt.rna.tf32.f32 %0, %1;" : "=r"(r) : "f"(x));
    return __uint_as_float(r);
}

// ---------------------------------------------------------------------------
// device-side e3nn constants
// ---------------------------------------------------------------------------
__device__ float su2_cg(int j1, int m1, int j2, int m2, int j3, int m3) {
    if (m1 + m2 != m3) return 0.f;
    int vmin = max(max(-j1 + j2 + m3, -j1 + m1), 0);
    int vmax = min(min(j2 + j3 + m1, j3 - j1 + j2), j3 + m3);
    float c = sqrtf((2.f * j3 + 1.f) * c_fact[j3 + j1 - j2] * c_fact[j3 - j1 + j2] *
                    c_fact[j1 + j2 - j3] / c_fact[j1 + j2 + j3 + 1] *
                    c_fact[j3 + m3] * c_fact[j3 - m3] /
                    (c_fact[j1 + m1] * c_fact[j1 - m1] * c_fact[j2 + m2] * c_fact[j2 - m2]));
    float s = 0.f;
    for (int v = vmin; v <= vmax; v++) {
        float t = c_fact[j2 + j3 + m1 - v] * c_fact[j1 - m1 + v] /
                  (c_fact[v] * c_fact[j3 - j1 + j2 - v] * c_fact[j3 + m3 - v] *
                   c_fact[v + j1 - j2 - m3]);
        s += ((v + j2 + m2) & 1) ? -t : t;
    }
    return c * s;
}

__device__ void build_q(int l, float2* q) {
    int d = 2 * l + 1;
    for (int i = 0; i < d * d; i++) q[i] = make_float2(0.f, 0.f);
    const float r = 0.7071067811865476f;
    for (int m = -l; m < 0; m++) {
        q[(l + m) * d + (l - m)] = make_float2(r, 0.f);
        q[(l + m) * d + (l + m)] = make_float2(0.f, -r);
    }
    q[l * d + l] = make_float2(1.f, 0.f);
    for (int m = 1; m <= l; m++) {
        float sg = (m & 1) ? -1.f : 1.f;
        q[(l + m) * d + (l + m)] = make_float2(sg * r, 0.f);
        q[(l + m) * d + (l - m)] = make_float2(0.f, sg * r);
    }
    float2 ph;
    switch (l & 3) {
        case 0: ph = make_float2(1.f, 0.f); break;
        case 1: ph = make_float2(0.f, -1.f); break;
        case 2: ph = make_float2(-1.f, 0.f); break;
        default: ph = make_float2(0.f, 1.f); break;
    }
    for (int i = 0; i < d * d; i++) {
        float2 a = q[i];
        q[i] = make_float2(a.x * ph.x - a.y * ph.y, a.x * ph.y + a.y * ph.x);
    }
}

__device__ void block_w3j(int l1, int l2, int l3, float* Cr, float* outs,
                          float2* q1s, float2* q2s, float2* q3s, float* red) {
    int tid = threadIdx.x;
    int d1 = 2 * l1 + 1, d2 = 2 * l2 + 1, d3 = 2 * l3 + 1;
    int sz = d1 * d2 * d3;
    for (int idx = tid; idx < sz; idx += blockDim.x) {
        int i = idx / (d2 * d3), rr = idx % (d2 * d3), k = rr / d3, m = rr % d3;
        Cr[idx] = su2_cg(l1, i - l1, l2, k - l2, l3, m - l3);
    }
    if (tid == 0) build_q(l1, q1s);
    else if (tid == 1) build_q(l2, q2s);
    else if (tid == 2) build_q(l3, q3s);
    __syncthreads();
    float ss = 0.f;
    for (int idx = tid; idx < sz; idx += blockDim.x) {
        int j = idx / (d2 * d3), rr = idx % (d2 * d3), lc = rr / d3, n = rr % d3;
        float re = 0.f;
        for (int i = 0; i < d1; i++) {
            float2 a = q1s[i * d1 + j];
            for (int k = 0; k < d2; k++) {
                float2 b = q2s[k * d2 + lc];
                float abr = a.x * b.x - a.y * b.y;
                float abi = a.x * b.y + a.y * b.x;
                for (int m = 0; m < d3; m++) {
                    float cv = Cr[(i * d2 + k) * d3 + m];
                    if (cv == 0.f) continue;
                    float2 g = q3s[m * d3 + n];
                    re += cv * (abr * g.x + abi * g.y);
                }
            }
        }
        outs[idx] = re;
        ss += re * re;
    }
    red[tid] = ss;
    __syncthreads();
    for (int st = 128; st > 0; st >>= 1) {
        if (tid < st) red[tid] += red[tid + st];
        __syncthreads();
    }
    float inv = rsqrtf(red[0]);
    for (int idx = tid; idx < sz; idx += blockDim.x) outs[idx] *= inv;
    __syncthreads();
}

// blocks 0-13: w3j; 14: silu; [15,287): weights; [287,2335): zero node_sum
__global__ void init_prep_kernel(const float* __restrict__ W0, const float* __restrict__ W1,
                                 const float* __restrict__ Wl1, const float* __restrict__ Wl2) {
    __shared__ float Cr[125];
    __shared__ float outs[125];
    __shared__ float rec2l[105];
    __shared__ float2 q1s[49], q2s[49], q3s[49];
    __shared__ float red[256];
    int tid = threadIdx.x, b = blockIdx.x;
    const int NT = 14;
    const int tl1[NT] = {0, 1, 2, 0, 1, 1, 2, 3, 0, 1, 2, 2, 3, 2};
    const int tl2[NT] = {0, 1, 2, 1, 0, 2, 1, 2, 2, 1, 0, 2, 1, 1};
    const int tl3[NT] = {0, 0, 0, 1, 1, 1, 1, 1, 2, 2, 2, 2, 2, 3};
    const int toff[NT] = {0, 1, 10, 35, 44, 53, 98, 143, 248, 273, 318, 343, 468, 0};

    if (b < 14) {
        int l1 = tl1[b], l2 = tl2[b], l3 = tl3[b];
        int sz = (2 * l1 + 1) * (2 * l2 + 1) * (2 * l3 + 1);
        block_w3j(l1, l2, l3, Cr, outs, q1s, q2s, q3s, red);
        if (b == 13) {
            for (int idx = tid; idx < sz; idx += blockDim.x) {
                g_c.rec2[idx] = outs[idx];
                rec2l[idx] = outs[idx];
            }
            __syncthreads();
            block_w3j(1, 1, 2, Cr, outs, q1s, q2s, q3s, red); // outs = rec1
            if (tid == 0) {
                float n0 = 0.3f, n1 = 0.5f, n2 = 0.81f;
                float inv = rsqrtf(n0 * n0 + n1 * n1 + n2 * n2);
                float ny[3] = {n1 * inv, n2 * inv, n0 * inv};
                float Y1[3];
                for (int i = 0; i < 3; i++) Y1[i] = 1.7320508075688772f * ny[i];
                float A[5] = {0, 0, 0, 0, 0};
                for (int i = 0; i < 3; i++)
                    for (int j = 0; j < 3; j++) {
                        float tt = Y1[i] * ny[j];
                        for (int k = 0; k < 5; k++) A[k] += tt * outs[(i * 3 + j) * 5 + k];
                    }
                float na = 0.f;
                for (int k = 0; k < 5; k++) na += A[k] * A[k];
                float s0 = sqrtf(5.f) * rsqrtf(na);
                g_c.sh_s0 = s0;
                float Y2[5];
                for (int k = 0; k < 5; k++) Y2[k] = A[k] * s0;
                float B[7] = {0, 0, 0, 0, 0, 0, 0};
                for (int i = 0; i < 5; i++)
                    for (int j = 0; j < 3; j++) {
                        float tt = Y2[i] * ny[j];
                        for (int k = 0; k < 7; k++) B[k] += tt * rec2l[(i * 3 + j) * 7 + k];
                    }
                float nb = 0.f;
                for (int k = 0; k < 7; k++) nb += B[k] * B[k];
                g_c.sh_s1 = sqrtf(7.f) * rsqrtf(nb);
            }
        } else {
            for (int idx = tid; idx < sz; idx += blockDim.x) {
                g_c.cg[toff[b] + idx] = outs[idx];
                if (b == 9) g_c.rec1[idx] = outs[idx];
            }
        }
    } else if (b == 14) {
        float part = 0.f;
        for (int i = tid; i < 20001; i += blockDim.x) {
            float z = -12.f + 24.f * (float)i / 20000.f;
            float s = z / (1.f + expf(-z));
            float phi = expf(-0.5f * z * z) * 0.3989422804014327f;
            float w = (i == 0 || i == 20000) ? 0.5f : 1.f;
            part += w * s * s * phi;
        }
        red[tid] = part;
        __syncthreads();
        for (int st = 128; st > 0; st >>= 1) {
            if (tid < st) red[tid] += red[tid + st];
            __syncthreads();
        }
        if (tid == 0) g_c.silu_c = rsqrtf(red[0] * (24.f / 20000.f));
    } else if (b < 287) {
        int i = (b - 15) * 256 + tid;
        if (i < 8192) {
            int k4 = i >> 8, rm = i & 255, u = rm >> 2, r = rm & 3;
            g_W0T[i] = W0[(k4 * 4 + r) * 64 + u];
            return;
        }
        i -= 8192;
        if (i < 20480) { g_W1r[i] = to_tf32(W1[i]); return; }
        i -= 20480;
        if (i < 20480) {
            int mp = i >> 6, u = i & 63, p = mp >> 6, um = mp & 63;
            g_Wg1[i] = to_tf32(Wl1[(um * 5 + p) * 64 + u]);
            return;
        }
        i -= 20480;
        if (i < 20480) {
            int mp = i >> 6, u = i & 63, p = mp >> 6, um = mp & 63;
            g_Wg2[i] = to_tf32(Wl2[(um * 5 + p) * 64 + u]);
        }
    } else {
        int i = (b - 287) * 256 + tid;
        ((float4*)g_node_sum)[i] = make_float4(0.f, 0.f, 0.f, 0.f);
    }
}

// ---------------------------------------------------------------------------
// K1: w = x@W0/sqrt(128) (4 edges/thread reg-blocked), SH, scatter, x->x2buf
// ---------------------------------------------------------------------------
__global__ void __launch_bounds__(256) k1_scatter(const float* __restrict__ vectors,
                                                  const float* __restrict__ x,
                                                  const int* __restrict__ senders) {
    __shared__ __align__(16) float xs[16][128];
    __shared__ float ws[16][64];
    __shared__ float Ys[16][16];
    __shared__ int sends[16];
    int tid = threadIdx.x;
    int eb = blockIdx.x * 16;
    if (tid < 16) sends[tid] = senders[eb + tid];
#pragma unroll
    for (int r = 0; r < 2; r++) {
        int idx = tid + r * 256;
        int e = idx >> 5, q = idx & 31;
        float4 v = ((const float4*)(x + (size_t)(eb + e) * 128))[q];
        *(float4*)&xs[e][q * 4] = v;
        ((float4*)(g_x2buf + (size_t)(eb + e) * 320))[q] =
            make_float4(to_tf32(v.x), to_tf32(v.y), to_tf32(v.z), to_tf32(v.w));
    }
    __syncthreads();
    int g = tid >> 6, u = tid & 63;
    float acc[4] = {0, 0, 0, 0};
#pragma unroll
    for (int k4 = 0; k4 < 32; k4++) {
        float4 w = *(const float4*)&g_W0T[k4 * 256 + u * 4];
#pragma unroll
        for (int c = 0; c < 4; c++) {
            float4 xv = *(const float4*)&xs[g * 4 + c][k4 * 4];
            acc[c] += w.x * xv.x + w.y * xv.y + w.z * xv.z + w.w * xv.w;
        }
    }
#pragma unroll
    for (int c = 0; c < 4; c++) ws[g * 4 + c][u] = acc[c] * 0.08838834764831845f;
    if (tid < 16) {
        int e = eb + tid;
        float vx = vectors[3 * e], vy = vectors[3 * e + 1], vz = vectors[3 * e + 2];
        float inv = rsqrtf(vx * vx + vy * vy + vz * vz);
        float ny[3] = {vy * inv, vz * inv, vx * inv};
        Ys[tid][0] = 1.f;
        float Y1[3];
#pragma unroll
        for (int i = 0; i < 3; i++) { Y1[i] = 1.7320508075688772f * ny[i]; Ys[tid][1 + i] = Y1[i]; }
        float Y2[5] = {0, 0, 0, 0, 0};
        for (int i = 0; i < 3; i++)
            for (int j = 0; j < 3; j++) {
                float t = Y1[i] * ny[j];
#pragma unroll
                for (int k = 0; k < 5; k++) Y2[k] += t * g_c.rec1[(i * 3 + j) * 5 + k];
            }
        float s0 = g_c.sh_s0;
#pragma unroll
        for (int k = 0; k < 5; k++) { Y2[k] *= s0; Ys[tid][4 + k] = Y2[k]; }
        float Y3[7] = {0, 0, 0, 0, 0, 0, 0};
        for (int i = 0; i < 5; i++)
            for (int j = 0; j < 3; j++) {
                float t = Y2[i] * ny[j];
#pragma unroll
                for (int k = 0; k < 7; k++) Y3[k] += t * g_c.rec2[(i * 3 + j) * 7 + k];
            }
        float s1 = g_c.sh_s1;
#pragma unroll
        for (int k = 0; k < 7; k++) Ys[tid][9 + k] = Y3[k] * s1;
    }
    __syncthreads();
#pragma unroll
    for (int it = 0; it < 16; it++) {
        int t = tid + it * 256;
        int e = t >> 8, q = t & 255;
        int uu = q >> 2, i0 = (q & 3) * 4;
        float w = ws[e][uu];
        atomicAdd((float4*)(g_node_sum + (size_t)sends[e] * 1024 + q * 4),
                  make_float4(w * Ys[e][i0], w * Ys[e][i0 + 1], w * Ys[e][i0 + 2], w * Ys[e][i0 + 3]));
    }
}

// ---------------------------------------------------------------------------
// K2a: tensor product per edge, split across 2 threads per (e,u)
// ---------------------------------------------------------------------------
template <int L1, int L2, int L3, int OFF>
__device__ __forceinline__ void tp_acc(const float* __restrict__ cgs, const float* wr,
                                       const float* vr, float* dst) {
    const int d1 = 2 * L1 + 1, d2 = 2 * L2 + 1, d3 = 2 * L3 + 1;
#pragma unroll
    for (int k = 0; k < d3; k++) dst[k] = 0.f;
#pragma unroll
    for (int i = 0; i < d1; i++) {
#pragma unroll
        for (int j = 0; j < d2; j++) {
            float t = wr[L1 * L1 + i] * vr[L2 * L2 + j];
#pragma unroll
            for (int k = 0; k < d3; k++) dst[k] += t * cgs[OFF + (i * d2 + j) * d3 + k];
        }
    }
}

__global__ void __launch_bounds__(256, 4) k2a_tp(const float* __restrict__ V,
                                                 const int* __restrict__ senders) {
    __shared__ float cgs[576];
    __shared__ float wYs[2][64 * 17];
    __shared__ __align__(16) float Vs[2][576];
    __shared__ int sends[2];
    int tid = threadIdx.x;
    int eb = blockIdx.x * 2;
    for (int t = tid; t < 573; t += 256) cgs[t] = g_c.cg[t];
    if (tid < 2) sends[tid] = senders[eb + tid];
    __syncthreads();
#pragma unroll
    for (int r = 0; r < 2; r++) {
        int idx = tid + r * 256;
        int sub = idx >> 8, q = idx & 255;
        float4 v = ((const float4*)(g_node_sum + (size_t)sends[sub] * 1024))[q];
        float* d = &wYs[sub][(q >> 2) * 17 + (q & 3) * 4];
        d[0] = v.x * 0.25f; d[1] = v.y * 0.25f; d[2] = v.z * 0.25f; d[3] = v.w * 0.25f;
    }
    for (int idx = tid; idx < 288; idx += 256) {
        int sub = idx / 144, r = idx - sub * 144;
        ((float4*)Vs[sub])[r] = ((const float4*)(V + (size_t)(eb + sub) * 576))[r];
    }
    __syncthreads();
    int sub = tid >> 7, half = (tid >> 6) & 1, u = tid & 63;
    int e = eb + sub;
    float wr[16], vr[9];
#pragma unroll
    for (int j = 0; j < 16; j++) wr[j] = wYs[sub][u * 17 + j];
#pragma unroll
    for (int j = 0; j < 9; j++) vr[j] = Vs[sub][u * 9 + j];

    const float R3 = 1.7320508075688772f, R5 = 2.2360679774997896f;
    if (half == 0) {
        float s0o[3], o1[5][3];
        tp_acc<0, 0, 0, 0>(cgs, wr, vr, &s0o[0]);
        tp_acc<1, 1, 0, 1>(cgs, wr, vr, &s0o[1]);
        tp_acc<2, 2, 0, 10>(cgs, wr, vr, &s0o[2]);
        tp_acc<0, 1, 1, 35>(cgs, wr, vr, o1[0]);
        tp_acc<1, 0, 1, 44>(cgs, wr, vr, o1[1]);
        tp_acc<1, 2, 1, 53>(cgs, wr, vr, o1[2]);
        tp_acc<2, 1, 1, 98>(cgs, wr, vr, o1[3]);
        tp_acc<3, 2, 1, 143>(cgs, wr, vr, o1[4]);
        float* x2p = g_x2buf + (size_t)e * 320 + 128 + u * 3;
        x2p[0] = to_tf32(s0o[0]); x2p[1] = to_tf32(s0o[1]); x2p[2] = to_tf32(s0o[2]);
#pragma unroll
        for (int i = 0; i < 3; i++)
#pragma unroll
            for (int p = 0; p < 5; p++)
                g_vbuf[((size_t)i * NEDGES + e) * 320 + p * 64 + u] = to_tf32(R3 * o1[p][i]);
    } else {
        float o2[5][5];
        tp_acc<0, 2, 2, 248>(cgs, wr, vr, o2[0]);
        tp_acc<1, 1, 2, 273>(cgs, wr, vr, o2[1]);
        tp_acc<2, 0, 2, 318>(cgs, wr, vr, o2[2]);
        tp_acc<2, 2, 2, 343>(cgs, wr, vr, o2[3]);
        tp_acc<3, 1, 2, 468>(cgs, wr, vr, o2[4]);
#pragma unroll
        for (int i = 0; i < 5; i++)
#pragma unroll
            for (int p = 0; p < 5; p++)
                g_vbuf[((size_t)(3 + i) * NEDGES + e) * 320 + p * 64 + u] = to_tf32(R5 * o2[p][i]);
    }
}

// ---------------------------------------------------------------------------
// K_gemm: 9 slices of [32768x320]@[320x64] via tf32 mma.sync, fused epilogues
// ---------------------------------------------------------------------------
__global__ void __launch_bounds__(256) k_gemm(float* __restrict__ Vout) {
    __shared__ __align__(16) float As[128 * 36];
    __shared__ __align__(16) float Bs[32 * 72];
    int tid = threadIdx.x, s = blockIdx.y;
    int e0 = blockIdx.x * 128;
    const float* Ab = (s < 8) ? g_vbuf + (size_t)s * NEDGES * 320 : g_x2buf;
    const float* Bm = (s < 3) ? g_Wg1 : (s < 8 ? g_Wg2 : g_W1r);
    int lane = tid & 31, warp = tid >> 5;
    int wm = warp & 3, wn = warp >> 2;
    int g = lane >> 2, tig = lane & 3;
    float acc[2][4][4];
#pragma unroll
    for (int a = 0; a < 2; a++)
#pragma unroll
        for (int b = 0; b < 4; b++)
#pragma unroll
            for (int c = 0; c < 4; c++) acc[a][b][c] = 0.f;

    for (int kc = 0; kc < 10; kc++) {
        __syncthreads();
        int k0 = kc * 32;
#pragma unroll
        for (int i = 0; i < 4; i++) {
            int idx = tid + i * 256;
            int row = idx >> 3, c4 = idx & 7;
            float4 v = ((const float4*)(Ab + (size_t)(e0 + row) * 320 + k0))[c4];
            *(float4*)&As[row * 36 + c4 * 4] = v;
        }
#pragma unroll
        for (int i = 0; i < 2; i++) {
            int idx = tid + i * 256;
            int k = idx >> 4, n4 = idx & 15;
            float4 v = ((const float4*)(Bm + (size_t)(k0 + k) * 64))[n4];
            *(float4*)&Bs[k * 72 + n4 * 4] = v;
        }
        __syncthreads();
#pragma unroll
        for (int ks = 0; ks < 4; ks++) {
            int kb = ks * 8;
            unsigned af[2][4], bf[4][2];
#pragma unroll
            for (int tm = 0; tm < 2; tm++) {
                int r = wm * 32 + tm * 16 + g;
                af[tm][0] = __float_as_uint(As[r * 36 + kb + tig]);
                af[tm][1] = __float_as_uint(As[(r + 8) * 36 + kb + tig]);
                af[tm][2] = __float_as_uint(As[r * 36 + kb + tig + 4]);
                af[tm][3] = __float_as_uint(As[(r + 8) * 36 + kb + tig + 4]);
            }
#pragma unroll
            for (int tn = 0; tn < 4; tn++) {
                int c = wn * 32 + tn * 8 + g;
                bf[tn][0] = __float_as_uint(Bs[(kb + tig) * 72 + c]);
                bf[tn][1] = __float_as_uint(Bs[(kb + tig + 4) * 72 + c]);
            }
#pragma unroll
            for (int tm = 0; tm < 2; tm++)
#pragma unroll
                for (int tn = 0; tn < 4; tn++) {
                    asm volatile(
                        "mma.sync.aligned.m16n8k8.row.col.f32.tf32.tf32.f32 "
                        "{%0,%1,%2,%3}, {%4,%5,%6,%7}, {%8,%9}, {%0,%1,%2,%3};\n"
                        : "+f"(acc[tm][tn][0]), "+f"(acc[tm][tn][1]),
                          "+f"(acc[tm][tn][2]), "+f"(acc[tm][tn][3])
                        : "r"(af[tm][0]), "r"(af[tm][1]), "r"(af[tm][2]), "r"(af[tm][3]),
                          "r"(bf[tn][0]), "r"(bf[tn][1]));
                }
        }
    }

    const float scale = 0.05590169943749474f; // 1/sqrt(320)
    float silu_c = g_c.silu_c;
#pragma unroll
    for (int tm = 0; tm < 2; tm++)
#pragma unroll
        for (int tn = 0; tn < 4; tn++)
#pragma unroll
            for (int q = 0; q < 4; q++) {
                int r = wm * 32 + tm * 16 + g + ((q >= 2) ? 8 : 0);
                int u = wn * 32 + tn * 8 + 2 * tig + (q & 1);
                int e = e0 + r;
                float v = acc[tm][tn][q] * scale;
                if (s < 3) Vout[(size_t)e * 576 + 64 + u * 3 + s] = v;
                else if (s < 8) Vout[(size_t)e * 576 + 256 + u * 5 + (s - 3)] = v;
                else g_h1[(size_t)e * 64 + u] = silu_c * v / (1.f + __expf(-v));
            }
}

// ---------------------------------------------------------------------------
// K3: MLP layers 2+3, envelope, xout, zero Vout scalar block
// ---------------------------------------------------------------------------
__global__ void __launch_bounds__(256) k3_mlp(const float* __restrict__ vectors,
                                              const float* __restrict__ W2,
                                              const float* __restrict__ W3,
                                              float* __restrict__ xout,
                                              float* __restrict__ Vout) {
    __shared__ float h1s[4][64], h2s[4][64];
    int tid = threadIdx.x, sub = tid >> 6, u = tid & 63;
    int e = blockIdx.x * 4 + sub;
    h1s[sub][u] = g_h1[(size_t)e * 64 + u];
    float silu_c = g_c.silu_c;
    __syncthreads();
    float acc = 0.f;
#pragma unroll 8
    for (int k = 0; k < 64; k++) acc += h1s[sub][k] * W2[k * 64 + u];
    float z = acc * 0.125f;
    h2s[sub][u] = silu_c * z / (1.f + __expf(-z));
    __syncthreads();
    acc = 0.f;
#pragma unroll 8
    for (int k = 0; k < 64; k++) acc += h2s[sub][k] * W3[k * 64 + u];
    float vx = vectors[3 * e], vy = vectors[3 * e + 1], vz = vectors[3 * e + 2];
    float d = sqrtf(vx * vx + vy * vy + vz * vz);
    float d3 = d * d * d, d6 = d3 * d3;
    float env = (d < 1.f) ? 1.f + d6 * (-28.f + d * (48.f - 21.f * d)) : 0.f;
    xout[(size_t)e * 64 + u] = env * acc * 0.125f;
    Vout[(size_t)e * 576 + u] = 0.f;
}

// ---------------------------------------------------------------------------
extern "C" void kernel_launch(void* const* d_in, const int* in_sizes, int n_in,
                              void* d_out, int out_size) {
    const float* vectors = (const float*)d_in[0];
    const float* x       = (const float*)d_in[1];
    const float* V       = (const float*)d_in[2];
    const int*   senders = (const int*)d_in[3];
    const float* W0      = (const float*)d_in[4];
    const float* W1      = (const float*)d_in[5];
    const float* W2      = (const float*)d_in[6];
    const float* W3      = (const float*)d_in[7];
    const float* Wl1     = (const float*)d_in[8];
    const float* Wl2     = (const float*)d_in[9];
    float* xout = (float*)d_out;
    float* Vout = xout + (size_t)NEDGES * 64;

    init_prep_kernel<<<2335, 256>>>(W0, W1, Wl1, Wl2);
    k1_scatter<<<2048, 256>>>(vectors, x, senders);
    k2a_tp<<<16384, 256>>>(V, senders);
    dim3 gg(256, 9);
    k_gemm<<<gg, 256>>>(Vout);
    k3_mlp<<<8192, 256>>>(vectors, W2, W3, xout, Vout);
}

// round 8
// speedup vs baseline: 1.5922x; 1.5922x over previous
#include <cuda_runtime.h>
#include <math.h>

#define NNODES 2048
#define NEDGES 32768

__constant__ float c_fact[16] = {
    1.f, 1.f, 2.f, 6.f, 24.f, 120.f, 720.f, 5040.f, 40320.f, 362880.f,
    3628800.f, 39916800.f, 479001600.f, 6227020800.f, 87178291200.f, 1307674368000.f};

struct DevConsts {
    float cg[576];
    float rec1[45];
    float rec2[105];
    float sh_s0, sh_s1, silu_c;
};
__device__ DevConsts g_c;

__device__ __align__(16) float g_node_sum[NNODES * 1024];
__device__ __align__(16) float g_W0T[8192];
__device__ __align__(16) float g_Wg1[20480];
__device__ __align__(16) float g_Wg2[20480];
__device__ __align__(16) float g_W1r[20480];
__device__ __align__(16) float g_vbuf[(size_t)8 * NEDGES * 320];
__device__ __align__(16) float g_x2buf[(size_t)NEDGES * 320];
__device__ __align__(16) float g_h1[(size_t)NEDGES * 64];

__device__ __forceinline__ float to_tf32(float x) {
    unsigned r;
    asm("cvt.rna.tf32.f32 %0, %1;" : "=r"(r) : "f"(x));
    return __uint_as_float(r);
}

__device__ __forceinline__ void cp16(unsigned dst, const void* src) {
    asm volatile("cp.async.cg.shared.global [%0], [%1], 16;\n" :: "r"(dst), "l"(src));
}

// ---------------------------------------------------------------------------
// device-side e3nn constants
// ---------------------------------------------------------------------------
__device__ float su2_cg(int j1, int m1, int j2, int m2, int j3, int m3) {
    if (m1 + m2 != m3) return 0.f;
    int vmin = max(max(-j1 + j2 + m3, -j1 + m1), 0);
    int vmax = min(min(j2 + j3 + m1, j3 - j1 + j2), j3 + m3);
    float c = sqrtf((2.f * j3 + 1.f) * c_fact[j3 + j1 - j2] * c_fact[j3 - j1 + j2] *
                    c_fact[j1 + j2 - j3] / c_fact[j1 + j2 + j3 + 1] *
                    c_fact[j3 + m3] * c_fact[j3 - m3] /
                    (c_fact[j1 + m1] * c_fact[j1 - m1] * c_fact[j2 + m2] * c_fact[j2 - m2]));
    float s = 0.f;
    for (int v = vmin; v <= vmax; v++) {
        float t = c_fact[j2 + j3 + m1 - v] * c_fact[j1 - m1 + v] /
                  (c_fact[v] * c_fact[j3 - j1 + j2 - v] * c_fact[j3 + m3 - v] *
                   c_fact[v + j1 - j2 - m3]);
        s += ((v + j2 + m2) & 1) ? -t : t;
    }
    return c * s;
}

__device__ void build_q(int l, float2* q) {
    int d = 2 * l + 1;
    for (int i = 0; i < d * d; i++) q[i] = make_float2(0.f, 0.f);
    const float r = 0.7071067811865476f;
    for (int m = -l; m < 0; m++) {
        q[(l + m) * d + (l - m)] = make_float2(r, 0.f);
        q[(l + m) * d + (l + m)] = make_float2(0.f, -r);
    }
    q[l * d + l] = make_float2(1.f, 0.f);
    for (int m = 1; m <= l; m++) {
        float sg = (m & 1) ? -1.f : 1.f;
        q[(l + m) * d + (l + m)] = make_float2(sg * r, 0.f);
        q[(l + m) * d + (l - m)] = make_float2(0.f, sg * r);
    }
    float2 ph;
    switch (l & 3) {
        case 0: ph = make_float2(1.f, 0.f); break;
        case 1: ph = make_float2(0.f, -1.f); break;
        case 2: ph = make_float2(-1.f, 0.f); break;
        default: ph = make_float2(0.f, 1.f); break;
    }
    for (int i = 0; i < d * d; i++) {
        float2 a = q[i];
        q[i] = make_float2(a.x * ph.x - a.y * ph.y, a.x * ph.y + a.y * ph.x);
    }
}

__device__ void block_w3j(int l1, int l2, int l3, float* Cr, float* outs,
                          float2* q1s, float2* q2s, float2* q3s, float* red) {
    int tid = threadIdx.x;
    int d1 = 2 * l1 + 1, d2 = 2 * l2 + 1, d3 = 2 * l3 + 1;
    int sz = d1 * d2 * d3;
    for (int idx = tid; idx < sz; idx += blockDim.x) {
        int i = idx / (d2 * d3), rr = idx % (d2 * d3), k = rr / d3, m = rr % d3;
        Cr[idx] = su2_cg(l1, i - l1, l2, k - l2, l3, m - l3);
    }
    if (tid == 0) build_q(l1, q1s);
    else if (tid == 1) build_q(l2, q2s);
    else if (tid == 2) build_q(l3, q3s);
    __syncthreads();
    float ss = 0.f;
    for (int idx = tid; idx < sz; idx += blockDim.x) {
        int j = idx / (d2 * d3), rr = idx % (d2 * d3), lc = rr / d3, n = rr % d3;
        float re = 0.f;
        for (int i = 0; i < d1; i++) {
            float2 a = q1s[i * d1 + j];
            for (int k = 0; k < d2; k++) {
                float2 b = q2s[k * d2 + lc];
                float abr = a.x * b.x - a.y * b.y;
                float abi = a.x * b.y + a.y * b.x;
                for (int m = 0; m < d3; m++) {
                    float cv = Cr[(i * d2 + k) * d3 + m];
                    if (cv == 0.f) continue;
                    float2 g = q3s[m * d3 + n];
                    re += cv * (abr * g.x + abi * g.y);
                }
            }
        }
        outs[idx] = re;
        ss += re * re;
    }
    red[tid] = ss;
    __syncthreads();
    for (int st = 128; st > 0; st >>= 1) {
        if (tid < st) red[tid] += red[tid + st];
        __syncthreads();
    }
    float inv = rsqrtf(red[0]);
    for (int idx = tid; idx < sz; idx += blockDim.x) outs[idx] *= inv;
    __syncthreads();
}

// blocks 0-13: w3j; 14: silu; [15,287): weights; [287,2335): zero node_sum
__global__ void init_prep_kernel(const float* __restrict__ W0, const float* __restrict__ W1,
                                 const float* __restrict__ Wl1, const float* __restrict__ Wl2) {
    __shared__ float Cr[125];
    __shared__ float outs[125];
    __shared__ float rec2l[105];
    __shared__ float2 q1s[49], q2s[49], q3s[49];
    __shared__ float red[256];
    int tid = threadIdx.x, b = blockIdx.x;
    const int NT = 14;
    const int tl1[NT] = {0, 1, 2, 0, 1, 1, 2, 3, 0, 1, 2, 2, 3, 2};
    const int tl2[NT] = {0, 1, 2, 1, 0, 2, 1, 2, 2, 1, 0, 2, 1, 1};
    const int tl3[NT] = {0, 0, 0, 1, 1, 1, 1, 1, 2, 2, 2, 2, 2, 3};
    const int toff[NT] = {0, 1, 10, 35, 44, 53, 98, 143, 248, 273, 318, 343, 468, 0};

    if (b < 14) {
        int l1 = tl1[b], l2 = tl2[b], l3 = tl3[b];
        int sz = (2 * l1 + 1) * (2 * l2 + 1) * (2 * l3 + 1);
        block_w3j(l1, l2, l3, Cr, outs, q1s, q2s, q3s, red);
        if (b == 13) {
            for (int idx = tid; idx < sz; idx += blockDim.x) {
                g_c.rec2[idx] = outs[idx];
                rec2l[idx] = outs[idx];
            }
            __syncthreads();
            block_w3j(1, 1, 2, Cr, outs, q1s, q2s, q3s, red); // outs = rec1
            if (tid == 0) {
                float n0 = 0.3f, n1 = 0.5f, n2 = 0.81f;
                float inv = rsqrtf(n0 * n0 + n1 * n1 + n2 * n2);
                float ny[3] = {n1 * inv, n2 * inv, n0 * inv};
                float Y1[3];
                for (int i = 0; i < 3; i++) Y1[i] = 1.7320508075688772f * ny[i];
                float A[5] = {0, 0, 0, 0, 0};
                for (int i = 0; i < 3; i++)
                    for (int j = 0; j < 3; j++) {
                        float tt = Y1[i] * ny[j];
                        for (int k = 0; k < 5; k++) A[k] += tt * outs[(i * 3 + j) * 5 + k];
                    }
                float na = 0.f;
                for (int k = 0; k < 5; k++) na += A[k] * A[k];
                float s0 = sqrtf(5.f) * rsqrtf(na);
                g_c.sh_s0 = s0;
                float Y2[5];
                for (int k = 0; k < 5; k++) Y2[k] = A[k] * s0;
                float B[7] = {0, 0, 0, 0, 0, 0, 0};
                for (int i = 0; i < 5; i++)
                    for (int j = 0; j < 3; j++) {
                        float tt = Y2[i] * ny[j];
                        for (int k = 0; k < 7; k++) B[k] += tt * rec2l[(i * 3 + j) * 7 + k];
                    }
                float nb = 0.f;
                for (int k = 0; k < 7; k++) nb += B[k] * B[k];
                g_c.sh_s1 = sqrtf(7.f) * rsqrtf(nb);
            }
        } else {
            for (int idx = tid; idx < sz; idx += blockDim.x) {
                g_c.cg[toff[b] + idx] = outs[idx];
                if (b == 9) g_c.rec1[idx] = outs[idx];
            }
        }
    } else if (b == 14) {
        float part = 0.f;
        for (int i = tid; i < 20001; i += blockDim.x) {
            float z = -12.f + 24.f * (float)i / 20000.f;
            float s = z / (1.f + expf(-z));
            float phi = expf(-0.5f * z * z) * 0.3989422804014327f;
            float w = (i == 0 || i == 20000) ? 0.5f : 1.f;
            part += w * s * s * phi;
        }
        red[tid] = part;
        __syncthreads();
        for (int st = 128; st > 0; st >>= 1) {
            if (tid < st) red[tid] += red[tid + st];
            __syncthreads();
        }
        if (tid == 0) g_c.silu_c = rsqrtf(red[0] * (24.f / 20000.f));
    } else if (b < 287) {
        int i = (b - 15) * 256 + tid;
        if (i < 8192) {
            int k4 = i >> 8, rm = i & 255, u = rm >> 2, r = rm & 3;
            g_W0T[i] = W0[(k4 * 4 + r) * 64 + u];
            return;
        }
        i -= 8192;
        if (i < 20480) { g_W1r[i] = to_tf32(W1[i]); return; }
        i -= 20480;
        if (i < 20480) {
            int mp = i >> 6, u = i & 63, p = mp >> 6, um = mp & 63;
            g_Wg1[i] = to_tf32(Wl1[(um * 5 + p) * 64 + u]);
            return;
        }
        i -= 20480;
        if (i < 20480) {
            int mp = i >> 6, u = i & 63, p = mp >> 6, um = mp & 63;
            g_Wg2[i] = to_tf32(Wl2[(um * 5 + p) * 64 + u]);
        }
    } else {
        int i = (b - 287) * 256 + tid;
        ((float4*)g_node_sum)[i] = make_float4(0.f, 0.f, 0.f, 0.f);
    }
}

// ---------------------------------------------------------------------------
// K1: w = x@W0/sqrt(128) (4 edges/thread reg-blocked), SH, scatter, x->x2buf
// ---------------------------------------------------------------------------
__global__ void __launch_bounds__(256) k1_scatter(const float* __restrict__ vectors,
                                                  const float* __restrict__ x,
                                                  const int* __restrict__ senders) {
    __shared__ __align__(16) float xs[16][128];
    __shared__ float ws[16][64];
    __shared__ float Ys[16][16];
    __shared__ int sends[16];
    int tid = threadIdx.x;
    int eb = blockIdx.x * 16;
    if (tid < 16) sends[tid] = senders[eb + tid];
#pragma unroll
    for (int r = 0; r < 2; r++) {
        int idx = tid + r * 256;
        int e = idx >> 5, q = idx & 31;
        float4 v = ((const float4*)(x + (size_t)(eb + e) * 128))[q];
        *(float4*)&xs[e][q * 4] = v;
        ((float4*)(g_x2buf + (size_t)(eb + e) * 320))[q] =
            make_float4(to_tf32(v.x), to_tf32(v.y), to_tf32(v.z), to_tf32(v.w));
    }
    __syncthreads();
    int g = tid >> 6, u = tid & 63;
    float acc[4] = {0, 0, 0, 0};
#pragma unroll
    for (int k4 = 0; k4 < 32; k4++) {
        float4 w = *(const float4*)&g_W0T[k4 * 256 + u * 4];
#pragma unroll
        for (int c = 0; c < 4; c++) {
            float4 xv = *(const float4*)&xs[g * 4 + c][k4 * 4];
            acc[c] += w.x * xv.x + w.y * xv.y + w.z * xv.z + w.w * xv.w;
        }
    }
#pragma unroll
    for (int c = 0; c < 4; c++) ws[g * 4 + c][u] = acc[c] * 0.08838834764831845f;
    if (tid < 16) {
        int e = eb + tid;
        float vx = vectors[3 * e], vy = vectors[3 * e + 1], vz = vectors[3 * e + 2];
        float inv = rsqrtf(vx * vx + vy * vy + vz * vz);
        float ny[3] = {vy * inv, vz * inv, vx * inv};
        Ys[tid][0] = 1.f;
        float Y1[3];
#pragma unroll
        for (int i = 0; i < 3; i++) { Y1[i] = 1.7320508075688772f * ny[i]; Ys[tid][1 + i] = Y1[i]; }
        float Y2[5] = {0, 0, 0, 0, 0};
        for (int i = 0; i < 3; i++)
            for (int j = 0; j < 3; j++) {
                float t = Y1[i] * ny[j];
#pragma unroll
                for (int k = 0; k < 5; k++) Y2[k] += t * g_c.rec1[(i * 3 + j) * 5 + k];
            }
        float s0 = g_c.sh_s0;
#pragma unroll
        for (int k = 0; k < 5; k++) { Y2[k] *= s0; Ys[tid][4 + k] = Y2[k]; }
        float Y3[7] = {0, 0, 0, 0, 0, 0, 0};
        for (int i = 0; i < 5; i++)
            for (int j = 0; j < 3; j++) {
                float t = Y2[i] * ny[j];
#pragma unroll
                for (int k = 0; k < 7; k++) Y3[k] += t * g_c.rec2[(i * 3 + j) * 7 + k];
            }
        float s1 = g_c.sh_s1;
#pragma unroll
        for (int k = 0; k < 7; k++) Ys[tid][9 + k] = Y3[k] * s1;
    }
    __syncthreads();
#pragma unroll
    for (int it = 0; it < 16; it++) {
        int t = tid + it * 256;
        int e = t >> 8, q = t & 255;
        int uu = q >> 2, i0 = (q & 3) * 4;
        float w = ws[e][uu];
        atomicAdd((float4*)(g_node_sum + (size_t)sends[e] * 1024 + q * 4),
                  make_float4(w * Ys[e][i0], w * Ys[e][i0 + 1], w * Ys[e][i0 + 2], w * Ys[e][i0 + 3]));
    }
}

// ---------------------------------------------------------------------------
// K2a: tensor product per edge (unsplit; 4 edges/block), modest occupancy push
// ---------------------------------------------------------------------------
template <int L1, int L2, int L3, int OFF>
__device__ __forceinline__ void tp_acc(const float* __restrict__ cgs, const float* wr,
                                       const float* vr, float* dst) {
    const int d1 = 2 * L1 + 1, d2 = 2 * L2 + 1, d3 = 2 * L3 + 1;
#pragma unroll
    for (int k = 0; k < d3; k++) dst[k] = 0.f;
#pragma unroll
    for (int i = 0; i < d1; i++) {
#pragma unroll
        for (int j = 0; j < d2; j++) {
            float t = wr[L1 * L1 + i] * vr[L2 * L2 + j];
#pragma unroll
            for (int k = 0; k < d3; k++) dst[k] += t * cgs[OFF + (i * d2 + j) * d3 + k];
        }
    }
}

__global__ void __launch_bounds__(256, 3) k2a_tp(const float* __restrict__ V,
                                                 const int* __restrict__ senders) {
    __shared__ float cgs[576];
    __shared__ float wYs[4][64 * 17];
    __shared__ __align__(16) float Vs[4][576];
    __shared__ int sends[4];
    int tid = threadIdx.x;
    int eb = blockIdx.x * 4;
    for (int t = tid; t < 573; t += 256) cgs[t] = g_c.cg[t];
    if (tid < 4) sends[tid] = senders[eb + tid];
    __syncthreads();
    for (int t = tid; t < 1024; t += 256) {
        int sub = t >> 8, r = t & 255;
        float4 v = ((const float4*)(g_node_sum + (size_t)sends[sub] * 1024))[r];
        int uu = r >> 2, j0 = (r & 3) * 4;
        float* d = &wYs[sub][uu * 17 + j0];
        d[0] = v.x * 0.25f; d[1] = v.y * 0.25f; d[2] = v.z * 0.25f; d[3] = v.w * 0.25f;
    }
    for (int t = tid; t < 576; t += 256) {
        int sub = t / 144, r = t - sub * 144;
        ((float4*)Vs[sub])[r] = ((const float4*)(V + (size_t)(eb + sub) * 576))[r];
    }
    __syncthreads();
    int sub = tid >> 6, u = tid & 63;
    int e = eb + sub;
    float wr[16], vr[9];
#pragma unroll
    for (int j = 0; j < 16; j++) wr[j] = wYs[sub][u * 17 + j];
#pragma unroll
    for (int j = 0; j < 9; j++) vr[j] = Vs[sub][u * 9 + j];

    float s0o[3], o1[5][3], o2[5][5];
    tp_acc<0, 0, 0, 0>(cgs, wr, vr, &s0o[0]);
    tp_acc<1, 1, 0, 1>(cgs, wr, vr, &s0o[1]);
    tp_acc<2, 2, 0, 10>(cgs, wr, vr, &s0o[2]);
    tp_acc<0, 1, 1, 35>(cgs, wr, vr, o1[0]);
    tp_acc<1, 0, 1, 44>(cgs, wr, vr, o1[1]);
    tp_acc<1, 2, 1, 53>(cgs, wr, vr, o1[2]);
    tp_acc<2, 1, 1, 98>(cgs, wr, vr, o1[3]);
    tp_acc<3, 2, 1, 143>(cgs, wr, vr, o1[4]);
    tp_acc<0, 2, 2, 248>(cgs, wr, vr, o2[0]);
    tp_acc<1, 1, 2, 273>(cgs, wr, vr, o2[1]);
    tp_acc<2, 0, 2, 318>(cgs, wr, vr, o2[2]);
    tp_acc<2, 2, 2, 343>(cgs, wr, vr, o2[3]);
    tp_acc<3, 1, 2, 468>(cgs, wr, vr, o2[4]);

    const float R3 = 1.7320508075688772f, R5 = 2.2360679774997896f;
    float* x2p = g_x2buf + (size_t)e * 320 + 128 + u * 3;
    x2p[0] = to_tf32(s0o[0]); x2p[1] = to_tf32(s0o[1]); x2p[2] = to_tf32(s0o[2]);
#pragma unroll
    for (int i = 0; i < 3; i++)
#pragma unroll
        for (int p = 0; p < 5; p++)
            g_vbuf[((size_t)i * NEDGES + e) * 320 + p * 64 + u] = to_tf32(R3 * o1[p][i]);
#pragma unroll
    for (int i = 0; i < 5; i++)
#pragma unroll
        for (int p = 0; p < 5; p++)
            g_vbuf[((size_t)(3 + i) * NEDGES + e) * 320 + p * 64 + u] = to_tf32(R5 * o2[p][i]);
}

// ---------------------------------------------------------------------------
// K_gemm: 9 slices of [32768x320]@[320x64], cp.async double-buffered pipeline
// ---------------------------------------------------------------------------
__global__ void __launch_bounds__(256, 4) k_gemm(float* __restrict__ Vout) {
    __shared__ __align__(16) float As[2][128 * 36];
    __shared__ __align__(16) float Bs[2][32 * 72];
    int tid = threadIdx.x, s = blockIdx.y;
    int e0 = blockIdx.x * 128;
    const float* Ab = (s < 8) ? g_vbuf + (size_t)s * NEDGES * 320 : g_x2buf;
    const float* Bm = (s < 3) ? g_Wg1 : (s < 8 ? g_Wg2 : g_W1r);
    int lane = tid & 31, warp = tid >> 5;
    int wm = warp & 3, wn = warp >> 2;
    int g = lane >> 2, tig = lane & 3;

    unsigned asA0 = (unsigned)__cvta_generic_to_shared(&As[0][0]);
    unsigned asA1 = (unsigned)__cvta_generic_to_shared(&As[1][0]);
    unsigned asB0 = (unsigned)__cvta_generic_to_shared(&Bs[0][0]);
    unsigned asB1 = (unsigned)__cvta_generic_to_shared(&Bs[1][0]);

    int arow = tid >> 1, ac4 = (tid & 1) * 4;   // A: 2 float4 per row slot; 4 iters
    int bk = tid >> 4, bn4 = tid & 15;          // B: 32x16 float4, 2 iters

    float acc[2][4][4];
#pragma unroll
    for (int a = 0; a < 2; a++)
#pragma unroll
        for (int b = 0; b < 4; b++)
#pragma unroll
            for (int c = 0; c < 4; c++) acc[a][b][c] = 0.f;

    // prologue: load chunk 0 into buf 0
    {
        int k0 = 0;
#pragma unroll
        for (int i = 0; i < 4; i++) {
            int idx = tid + i * 256;
            int row = idx >> 3, c4 = idx & 7;
            cp16(asA0 + (row * 36 + c4 * 4) * 4, Ab + (size_t)(e0 + row) * 320 + k0 + c4 * 4);
        }
#pragma unroll
        for (int i = 0; i < 2; i++) {
            int idx = tid + i * 256;
            int k = idx >> 4, n4 = idx & 15;
            cp16(asB0 + (k * 72 + n4 * 4) * 4, Bm + (size_t)(k0 + k) * 64 + n4 * 4);
        }
        asm volatile("cp.async.commit_group;\n");
    }

    for (int kc = 0; kc < 10; kc++) {
        int buf = kc & 1;
        __syncthreads(); // mma of kc-1 done everywhere before refilling buf^1... (see below)
        if (kc < 9) {
            int k0 = (kc + 1) * 32;
            unsigned dA = (buf == 0) ? asA1 : asA0;
            unsigned dB = (buf == 0) ? asB1 : asB0;
#pragma unroll
            for (int i = 0; i < 4; i++) {
                int idx = tid + i * 256;
                int row = idx >> 3, c4 = idx & 7;
                cp16(dA + (row * 36 + c4 * 4) * 4, Ab + (size_t)(e0 + row) * 320 + k0 + c4 * 4);
            }
#pragma unroll
            for (int i = 0; i < 2; i++) {
                int idx = tid + i * 256;
                int k = idx >> 4, n4 = idx & 15;
                cp16(dB + (k * 72 + n4 * 4) * 4, Bm + (size_t)(k0 + k) * 64 + n4 * 4);
            }
            asm volatile("cp.async.commit_group;\n");
            asm volatile("cp.async.wait_group 1;\n");
        } else {
            asm volatile("cp.async.wait_group 0;\n");
        }
        __syncthreads(); // chunk kc visible to all
        const float* Ac = As[buf];
        const float* Bc = Bs[buf];
#pragma unroll
        for (int ks = 0; ks < 4; ks++) {
            int kb = ks * 8;
            unsigned af[2][4], bf[4][2];
#pragma unroll
            for (int tm = 0; tm < 2; tm++) {
                int r = wm * 32 + tm * 16 + g;
                af[tm][0] = __float_as_uint(Ac[r * 36 + kb + tig]);
                af[tm][1] = __float_as_uint(Ac[(r + 8) * 36 + kb + tig]);
                af[tm][2] = __float_as_uint(Ac[r * 36 + kb + tig + 4]);
                af[tm][3] = __float_as_uint(Ac[(r + 8) * 36 + kb + tig + 4]);
            }
#pragma unroll
            for (int tn = 0; tn < 4; tn++) {
                int c = wn * 32 + tn * 8 + g;
                bf[tn][0] = __float_as_uint(Bc[(kb + tig) * 72 + c]);
                bf[tn][1] = __float_as_uint(Bc[(kb + tig + 4) * 72 + c]);
            }
#pragma unroll
            for (int tm = 0; tm < 2; tm++)
#pragma unroll
                for (int tn = 0; tn < 4; tn++) {
                    asm volatile(
                        "mma.sync.aligned.m16n8k8.row.col.f32.tf32.tf32.f32 "
                        "{%0,%1,%2,%3}, {%4,%5,%6,%7}, {%8,%9}, {%0,%1,%2,%3};\n"
                        : "+f"(acc[tm][tn][0]), "+f"(acc[tm][tn][1]),
                          "+f"(acc[tm][tn][2]), "+f"(acc[tm][tn][3])
                        : "r"(af[tm][0]), "r"(af[tm][1]), "r"(af[tm][2]), "r"(af[tm][3]),
                          "r"(bf[tn][0]), "r"(bf[tn][1]));
                }
        }
    }

    const float scale = 0.05590169943749474f; // 1/sqrt(320)
    float silu_c = g_c.silu_c;
#pragma unroll
    for (int tm = 0; tm < 2; tm++)
#pragma unroll
        for (int tn = 0; tn < 4; tn++)
#pragma unroll
            for (int q = 0; q < 4; q++) {
                int r = wm * 32 + tm * 16 + g + ((q >= 2) ? 8 : 0);
                int u = wn * 32 + tn * 8 + 2 * tig + (q & 1);
                int e = e0 + r;
                float v = acc[tm][tn][q] * scale;
                if (s < 3) Vout[(size_t)e * 576 + 64 + u * 3 + s] = v;
                else if (s < 8) Vout[(size_t)e * 576 + 256 + u * 5 + (s - 3)] = v;
                else g_h1[(size_t)e * 64 + u] = silu_c * v / (1.f + __expf(-v));
            }
}

// ---------------------------------------------------------------------------
// K3: MLP layers 2+3, envelope, xout, zero Vout scalar block
// ---------------------------------------------------------------------------
__global__ void __launch_bounds__(256) k3_mlp(const float* __restrict__ vectors,
                                              const float* __restrict__ W2,
                                              const float* __restrict__ W3,
                                              float* __restrict__ xout,
                                              float* __restrict__ Vout) {
    __shared__ float h1s[4][64], h2s[4][64];
    int tid = threadIdx.x, sub = tid >> 6, u = tid & 63;
    int e = blockIdx.x * 4 + sub;
    h1s[sub][u] = g_h1[(size_t)e * 64 + u];
    float silu_c = g_c.silu_c;
    __syncthreads();
    float acc = 0.f;
#pragma unroll 8
    for (int k = 0; k < 64; k++) acc += h1s[sub][k] * W2[k * 64 + u];
    float z = acc * 0.125f;
    h2s[sub][u] = silu_c * z / (1.f + __expf(-z));
    __syncthreads();
    acc = 0.f;
#pragma unroll 8
    for (int k = 0; k < 64; k++) acc += h2s[sub][k] * W3[k * 64 + u];
    float vx = vectors[3 * e], vy = vectors[3 * e + 1], vz = vectors[3 * e + 2];
    float d = sqrtf(vx * vx + vy * vy + vz * vz);
    float d3 = d * d * d, d6 = d3 * d3;
    float env = (d < 1.f) ? 1.f + d6 * (-28.f + d * (48.f - 21.f * d)) : 0.f;
    xout[(size_t)e * 64 + u] = env * acc * 0.125f;
    Vout[(size_t)e * 576 + u] = 0.f;
}

// ---------------------------------------------------------------------------
extern "C" void kernel_launch(void* const* d_in, const int* in_sizes, int n_in,
                              void* d_out, int out_size) {
    const float* vectors = (const float*)d_in[0];
    const float* x       = (const float*)d_in[1];
    const float* V       = (const float*)d_in[2];
    const int*   senders = (const int*)d_in[3];
    const float* W0      = (const float*)d_in[4];
    const float* W1      = (const float*)d_in[5];
    const float* W2      = (const float*)d_in[6];
    const float* W3      = (const float*)d_in[7];
    const float* Wl1     = (const float*)d_in[8];
    const float* Wl2     = (const float*)d_in[9];
    float* xout = (float*)d_out;
    float* Vout = xout + (size_t)NEDGES * 64;

    init_prep_kernel<<<2335, 256>>>(W0, W1, Wl1, Wl2);
    k1_scatter<<<2048, 256>>>(vectors, x, senders);
    k2a_tp<<<8192, 256>>>(V, senders);
    dim3 gg(256, 9);
    k_gemm<<<gg, 256>>>(Vout);
    k3_mlp<<<8192, 256>>>(vectors, W2, W3, xout, Vout);
}

// round 10
// speedup vs baseline: 1.8439x; 1.1581x over previous
#include <cuda_runtime.h>
#include <math.h>

#define NNODES 2048
#define NEDGES 32768

// ===========================================================================
// Compile-time e3nn real-basis Wigner 3j machinery
// ===========================================================================
__host__ __device__ constexpr double cfact(int n) {
    double r = 1.0;
    for (int i = 2; i <= n; i++) r *= (double)i;
    return r;
}
__host__ __device__ constexpr double csqrt(double x) {
    if (x <= 0.0) return 0.0;
    double g = x < 1.0 ? 1.0 : x;
    for (int i = 0; i < 80; i++) g = 0.5 * (g + x / g);
    return g;
}
struct CD { double re; double im; };
__host__ __device__ constexpr CD cmul(CD a, CD b) {
    return {a.re * b.re - a.im * b.im, a.re * b.im + a.im * b.re};
}

__host__ __device__ constexpr double su2cg(int j1, int m1, int j2, int m2, int j3, int m3) {
    if (m1 + m2 != m3) return 0.0;
    int vmin = -j1 + j2 + m3;
    if (-j1 + m1 > vmin) vmin = -j1 + m1;
    if (0 > vmin) vmin = 0;
    int vmax = j2 + j3 + m1;
    if (j3 - j1 + j2 < vmax) vmax = j3 - j1 + j2;
    if (j3 + m3 < vmax) vmax = j3 + m3;
    double c = csqrt((2.0 * j3 + 1.0) * cfact(j3 + j1 - j2) * cfact(j3 - j1 + j2) *
                     cfact(j1 + j2 - j3) / cfact(j1 + j2 + j3 + 1) *
                     cfact(j3 + m3) * cfact(j3 - m3) /
                     (cfact(j1 + m1) * cfact(j1 - m1) * cfact(j2 + m2) * cfact(j2 - m2)));
    double s = 0.0;
    for (int v = vmin; v <= vmax; v++) {
        double t = cfact(j2 + j3 + m1 - v) * cfact(j1 - m1 + v) /
                   (cfact(v) * cfact(j3 - j1 + j2 - v) * cfact(j3 + m3 - v) *
                    cfact(v + j1 - j2 - m3));
        s += ((v + j2 + m2) & 1) ? -t : t;
    }
    return c * s;
}

template <int L> struct QM { CD q[(2 * L + 1) * (2 * L + 1)]{}; };

template <int L> __host__ __device__ constexpr QM<L> buildq() {
    QM<L> Q{};
    constexpr int d = 2 * L + 1;
    const double r = csqrt(0.5);
    for (int m = -L; m < 0; m++) {
        Q.q[(L + m) * d + (L - m)] = {r, 0.0};
        Q.q[(L + m) * d + (L + m)] = {0.0, -r};
    }
    Q.q[L * d + L] = {1.0, 0.0};
    for (int m = 1; m <= L; m++) {
        double sg = (m & 1) ? -1.0 : 1.0;
        Q.q[(L + m) * d + (L + m)] = {sg * r, 0.0};
        Q.q[(L + m) * d + (L - m)] = {0.0, sg * r};
    }
    CD ph = (L % 4 == 0) ? CD{1.0, 0.0}
          : (L % 4 == 1) ? CD{0.0, -1.0}
          : (L % 4 == 2) ? CD{-1.0, 0.0}
                         : CD{0.0, 1.0};
    for (int i = 0; i < d * d; i++) Q.q[i] = cmul(Q.q[i], ph);
    return Q;
}

template <int L1, int L2, int L3> struct W3J {
    float c[(2 * L1 + 1) * (2 * L2 + 1) * (2 * L3 + 1)]{};
};

template <int L1, int L2, int L3> __host__ __device__ constexpr W3J<L1, L2, L3> w3j() {
    constexpr int d1 = 2 * L1 + 1, d2 = 2 * L2 + 1, d3 = 2 * L3 + 1;
    double C[d1 * d2 * d3]{};
    for (int m1 = -L1; m1 <= L1; m1++)
        for (int m2 = -L2; m2 <= L2; m2++) {
            int m3 = m1 + m2;
            if (m3 >= -L3 && m3 <= L3)
                C[((L1 + m1) * d2 + (L2 + m2)) * d3 + (L3 + m3)] = su2cg(L1, m1, L2, m2, L3, m3);
        }
    QM<L1> q1 = buildq<L1>();
    QM<L2> q2 = buildq<L2>();
    QM<L3> q3 = buildq<L3>();
    double out[d1 * d2 * d3]{};
    double ss = 0.0;
    for (int j = 0; j < d1; j++)
        for (int l = 0; l < d2; l++)
            for (int n = 0; n < d3; n++) {
                double re = 0.0;
                for (int i = 0; i < d1; i++)
                    for (int k = 0; k < d2; k++) {
                        CD ab = cmul(q1.q[i * d1 + j], q2.q[k * d2 + l]);
                        for (int m = 0; m < d3; m++) {
                            double cv = C[(i * d2 + k) * d3 + m];
                            if (cv != 0.0) {
                                CD g = q3.q[m * d3 + n];
                                re += cv * (ab.re * g.re + ab.im * g.im); // conj(g)
                            }
                        }
                    }
                out[(j * d2 + l) * d3 + n] = re;
                ss += re * re;
            }
    double inv = 1.0 / csqrt(ss);
    W3J<L1, L2, L3> R{};
    for (int idx = 0; idx < d1 * d2 * d3; idx++) R.c[idx] = (float)(out[idx] * inv);
    return R;
}

template <int L1, int L2, int L3> struct CGH {
    static constexpr W3J<L1, L2, L3> v = w3j<L1, L2, L3>();
};

__host__ __device__ constexpr bool rowAnyF(const float* c, int d2, int d3, int I, int J) {
    for (int k = 0; k < d3; k++)
        if (c[(I * d2 + J) * d3 + k] != 0.f) return true;
    return false;
}
template <int L1, int L2, int L3, int I, int J> struct RowAny {
    static constexpr bool value =
        rowAnyF(CGH<L1, L2, L3>::v.c, 2 * L2 + 1, 2 * L3 + 1, I, J);
};

// template-recursive TP with immediate constants, zero terms skipped
template <int L1, int L2, int L3, int I, int J, int K>
__device__ __forceinline__ void tp_k(float t, float* dst) {
    if constexpr (K < 2 * L3 + 1) {
        constexpr float cv = CGH<L1, L2, L3>::v.c[(I * (2 * L2 + 1) + J) * (2 * L3 + 1) + K];
        if constexpr (cv != 0.f) dst[K] += t * cv;
        tp_k<L1, L2, L3, I, J, K + 1>(t, dst);
    }
}
template <int L1, int L2, int L3, int I, int J>
__device__ __forceinline__ void tp_ij(const float* wr, const float* vr, float* dst) {
    if constexpr (J < 2 * L2 + 1) {
        if constexpr (RowAny<L1, L2, L3, I, J>::value) {
            float t = wr[L1 * L1 + I] * vr[L2 * L2 + J];
            tp_k<L1, L2, L3, I, J, 0>(t, dst);
        }
        tp_ij<L1, L2, L3, I, J + 1>(wr, vr, dst);
    }
}
template <int L1, int L2, int L3, int I>
__device__ __forceinline__ void tp_i(const float* wr, const float* vr, float* dst) {
    if constexpr (I < 2 * L1 + 1) {
        tp_ij<L1, L2, L3, I, 0>(wr, vr, dst);
        tp_i<L1, L2, L3, I + 1>(wr, vr, dst);
    }
}
template <int L1, int L2, int L3>
__device__ __forceinline__ void tp_full(const float* wr, const float* vr, float* dst) {
#pragma unroll
    for (int k = 0; k < 2 * L3 + 1; k++) dst[k] = 0.f;
    tp_i<L1, L2, L3, 0>(wr, vr, dst);
}

// SH recursion scales (constexpr mirror of reference _sh_scales)
__host__ __device__ constexpr double sh_scale(int which) {
    double n0 = 0.3, n1 = 0.5, n2 = 0.81;
    double inv = 1.0 / csqrt(n0 * n0 + n1 * n1 + n2 * n2);
    double ny[3] = {n1 * inv, n2 * inv, n0 * inv};
    constexpr W3J<1, 1, 2> cg112 = w3j<1, 1, 2>();
    constexpr W3J<2, 1, 3> cg213 = w3j<2, 1, 3>();
    double Y1[3] = {0, 0, 0};
    for (int i = 0; i < 3; i++) Y1[i] = csqrt(3.0) * ny[i];
    double A[5] = {0, 0, 0, 0, 0};
    for (int i = 0; i < 3; i++)
        for (int j = 0; j < 3; j++) {
            double t = Y1[i] * ny[j];
            for (int k = 0; k < 5; k++) A[k] += t * (double)cg112.c[(i * 3 + j) * 5 + k];
        }
    double na = 0;
    for (int k = 0; k < 5; k++) na += A[k] * A[k];
    double s0 = csqrt(5.0) / csqrt(na);
    if (which == 0) return s0;
    double Y2[5] = {0, 0, 0, 0, 0};
    for (int k = 0; k < 5; k++) Y2[k] = A[k] * s0;
    double B[7] = {0, 0, 0, 0, 0, 0, 0};
    for (int i = 0; i < 5; i++)
        for (int j = 0; j < 3; j++) {
            double t = Y2[i] * ny[j];
            for (int k = 0; k < 7; k++) B[k] += t * (double)cg213.c[(i * 3 + j) * 7 + k];
        }
    double nb = 0;
    for (int k = 0; k < 7; k++) nb += B[k] * B[k];
    return csqrt(7.0) / csqrt(nb);
}
constexpr float SH_S0 = (float)sh_scale(0);
constexpr float SH_S1 = (float)sh_scale(1);

// ===========================================================================
__device__ float g_silu_c;
__device__ __align__(16) float g_node_sum[NNODES * 1024];
__device__ __align__(16) float g_W0T[8192];
__device__ __align__(16) float g_Wg1[20480];
__device__ __align__(16) float g_Wg2[20480];
__device__ __align__(16) float g_W1r[20480];
__device__ __align__(16) float g_vbuf[(size_t)8 * NEDGES * 320];
__device__ __align__(16) float g_x2buf[(size_t)NEDGES * 320];
__device__ __align__(16) float g_h1[(size_t)NEDGES * 64];

__device__ __forceinline__ float to_tf32(float x) {
    unsigned r;
    asm("cvt.rna.tf32.f32 %0, %1;" : "=r"(r) : "f"(x));
    return __uint_as_float(r);
}
__device__ __forceinline__ void cp16(unsigned dst, const void* src) {
    asm volatile("cp.async.cg.shared.global [%0], [%1], 16;\n" :: "r"(dst), "l"(src));
}

// ---------------------------------------------------------------------------
// init: block 0 = silu_c; [1,273) = weight prep; [273,2321) = zero node_sum
// ---------------------------------------------------------------------------
__global__ void init_prep_kernel(const float* __restrict__ W0, const float* __restrict__ W1,
                                 const float* __restrict__ Wl1, const float* __restrict__ Wl2) {
    __shared__ float red[256];
    int tid = threadIdx.x, b = blockIdx.x;
    if (b == 0) {
        float part = 0.f;
        for (int i = tid; i < 20001; i += blockDim.x) {
            float z = -12.f + 24.f * (float)i / 20000.f;
            float s = z / (1.f + expf(-z));
            float phi = expf(-0.5f * z * z) * 0.3989422804014327f;
            float w = (i == 0 || i == 20000) ? 0.5f : 1.f;
            part += w * s * s * phi;
        }
        red[tid] = part;
        __syncthreads();
        for (int st = 128; st > 0; st >>= 1) {
            if (tid < st) red[tid] += red[tid + st];
            __syncthreads();
        }
        if (tid == 0) g_silu_c = rsqrtf(red[0] * (24.f / 20000.f));
    } else if (b < 273) {
        int i = (b - 1) * 256 + tid;
        if (i < 8192) {
            int k4 = i >> 8, rm = i & 255, u = rm >> 2, r = rm & 3;
            g_W0T[i] = W0[(k4 * 4 + r) * 64 + u];
            return;
        }
        i -= 8192;
        if (i < 20480) { g_W1r[i] = to_tf32(W1[i]); return; }
        i -= 20480;
        if (i < 20480) {
            int mp = i >> 6, u = i & 63, p = mp >> 6, um = mp & 63;
            g_Wg1[i] = to_tf32(Wl1[(um * 5 + p) * 64 + u]);
            return;
        }
        i -= 20480;
        if (i < 20480) {
            int mp = i >> 6, u = i & 63, p = mp >> 6, um = mp & 63;
            g_Wg2[i] = to_tf32(Wl2[(um * 5 + p) * 64 + u]);
        }
    } else {
        int i = (b - 273) * 256 + tid;
        ((float4*)g_node_sum)[i] = make_float4(0.f, 0.f, 0.f, 0.f);
    }
}

// ---------------------------------------------------------------------------
// K1: w = x@W0/sqrt(128), SH via constexpr recursion, scatter, x->x2buf
// ---------------------------------------------------------------------------
__global__ void __launch_bounds__(256) k1_scatter(const float* __restrict__ vectors,
                                                  const float* __restrict__ x,
                                                  const int* __restrict__ senders) {
    __shared__ __align__(16) float xs[16][128];
    __shared__ float ws[16][64];
    __shared__ float Ys[16][16];
    __shared__ int sends[16];
    int tid = threadIdx.x;
    int eb = blockIdx.x * 16;
    if (tid < 16) sends[tid] = senders[eb + tid];
#pragma unroll
    for (int r = 0; r < 2; r++) {
        int idx = tid + r * 256;
        int e = idx >> 5, q = idx & 31;
        float4 v = ((const float4*)(x + (size_t)(eb + e) * 128))[q];
        *(float4*)&xs[e][q * 4] = v;
        ((float4*)(g_x2buf + (size_t)(eb + e) * 320))[q] =
            make_float4(to_tf32(v.x), to_tf32(v.y), to_tf32(v.z), to_tf32(v.w));
    }
    __syncthreads();
    int g = tid >> 6, u = tid & 63;
    float acc[4] = {0, 0, 0, 0};
#pragma unroll
    for (int k4 = 0; k4 < 32; k4++) {
        float4 w = *(const float4*)&g_W0T[k4 * 256 + u * 4];
#pragma unroll
        for (int c = 0; c < 4; c++) {
            float4 xv = *(const float4*)&xs[g * 4 + c][k4 * 4];
            acc[c] += w.x * xv.x + w.y * xv.y + w.z * xv.z + w.w * xv.w;
        }
    }
#pragma unroll
    for (int c = 0; c < 4; c++) ws[g * 4 + c][u] = acc[c] * 0.08838834764831845f;
    if (tid < 16) {
        int e = eb + tid;
        float vx = vectors[3 * e], vy = vectors[3 * e + 1], vz = vectors[3 * e + 2];
        float inv = rsqrtf(vx * vx + vy * vy + vz * vz);
        float nb4[4] = {0.f, vy * inv, vz * inv, vx * inv};
        Ys[tid][0] = 1.f;
        float wb[4];
        wb[0] = 0.f;
#pragma unroll
        for (int i = 0; i < 3; i++) {
            wb[1 + i] = 1.7320508075688772f * nb4[1 + i];
            Ys[tid][1 + i] = wb[1 + i];
        }
        float Y2[5];
        tp_full<1, 1, 2>(wb, nb4, Y2);
        float wb2[9] = {0, 0, 0, 0, 0, 0, 0, 0, 0};
#pragma unroll
        for (int k = 0; k < 5; k++) {
            Y2[k] *= SH_S0;
            Ys[tid][4 + k] = Y2[k];
            wb2[4 + k] = Y2[k];
        }
        float Y3[7];
        tp_full<2, 1, 3>(wb2, nb4, Y3);
#pragma unroll
        for (int k = 0; k < 7; k++) Ys[tid][9 + k] = Y3[k] * SH_S1;
    }
    __syncthreads();
#pragma unroll
    for (int it = 0; it < 16; it++) {
        int t = tid + it * 256;
        int e = t >> 8, q = t & 255;
        int uu = q >> 2, i0 = (q & 3) * 4;
        float w = ws[e][uu];
        atomicAdd((float4*)(g_node_sum + (size_t)sends[e] * 1024 + q * 4),
                  make_float4(w * Ys[e][i0], w * Ys[e][i0 + 1], w * Ys[e][i0 + 2], w * Ys[e][i0 + 3]));
    }
}

// ---------------------------------------------------------------------------
// K2a: tensor product per edge, constexpr CG (FFMA-imm, zeros skipped)
// ---------------------------------------------------------------------------
__global__ void __launch_bounds__(256, 3) k2a_tp(const float* __restrict__ V,
                                                 const int* __restrict__ senders) {
    __shared__ float wYs[4][64 * 17];
    __shared__ __align__(16) float Vs[4][576];
    __shared__ int sends[4];
    int tid = threadIdx.x;
    int eb = blockIdx.x * 4;
    if (tid < 4) sends[tid] = senders[eb + tid];
    __syncthreads();
    for (int t = tid; t < 1024; t += 256) {
        int sub = t >> 8, r = t & 255;
        float4 v = ((const float4*)(g_node_sum + (size_t)sends[sub] * 1024))[r];
        int uu = r >> 2, j0 = (r & 3) * 4;
        float* d = &wYs[sub][uu * 17 + j0];
        d[0] = v.x * 0.25f; d[1] = v.y * 0.25f; d[2] = v.z * 0.25f; d[3] = v.w * 0.25f;
    }
    for (int t = tid; t < 576; t += 256) {
        int sub = t / 144, r = t - sub * 144;
        ((float4*)Vs[sub])[r] = ((const float4*)(V + (size_t)(eb + sub) * 576))[r];
    }
    __syncthreads();
    int sub = tid >> 6, u = tid & 63;
    int e = eb + sub;
    float wr[16], vr[9];
#pragma unroll
    for (int j = 0; j < 16; j++) wr[j] = wYs[sub][u * 17 + j];
#pragma unroll
    for (int j = 0; j < 9; j++) vr[j] = Vs[sub][u * 9 + j];

    const float R3 = 1.7320508075688772f, R5 = 2.2360679774997896f;
    // scalars
    {
        float s0o[3], t1[1];
        tp_full<0, 0, 0>(wr, vr, t1); s0o[0] = t1[0];
        tp_full<1, 1, 0>(wr, vr, t1); s0o[1] = t1[0];
        tp_full<2, 2, 0>(wr, vr, t1); s0o[2] = t1[0];
        float* x2p = g_x2buf + (size_t)e * 320 + 128 + u * 3;
        x2p[0] = to_tf32(s0o[0]); x2p[1] = to_tf32(s0o[1]); x2p[2] = to_tf32(s0o[2]);
    }
    // l=1 outputs
    {
        float o1[5][3];
        tp_full<0, 1, 1>(wr, vr, o1[0]);
        tp_full<1, 0, 1>(wr, vr, o1[1]);
        tp_full<1, 2, 1>(wr, vr, o1[2]);
        tp_full<2, 1, 1>(wr, vr, o1[3]);
        tp_full<3, 2, 1>(wr, vr, o1[4]);
#pragma unroll
        for (int i = 0; i < 3; i++)
#pragma unroll
            for (int p = 0; p < 5; p++)
                g_vbuf[((size_t)i * NEDGES + e) * 320 + p * 64 + u] = to_tf32(R3 * o1[p][i]);
    }
    // l=2 outputs
    {
        float o2[5][5];
        tp_full<0, 2, 2>(wr, vr, o2[0]);
        tp_full<1, 1, 2>(wr, vr, o2[1]);
        tp_full<2, 0, 2>(wr, vr, o2[2]);
        tp_full<2, 2, 2>(wr, vr, o2[3]);
        tp_full<3, 1, 2>(wr, vr, o2[4]);
#pragma unroll
        for (int i = 0; i < 5; i++)
#pragma unroll
            for (int p = 0; p < 5; p++)
                g_vbuf[((size_t)(3 + i) * NEDGES + e) * 320 + p * 64 + u] = to_tf32(R5 * o2[p][i]);
    }
}

// ---------------------------------------------------------------------------
// K_gemm: 9 slices of [32768x320]@[320x64], M-tile 64, cp.async 2-stage
// ---------------------------------------------------------------------------
__global__ void __launch_bounds__(256, 5) k_gemm(float* __restrict__ Vout) {
    __shared__ __align__(16) float As[2][64 * 36];
    __shared__ __align__(16) float Bs[2][32 * 72];
    int tid = threadIdx.x, s = blockIdx.y;
    int e0 = blockIdx.x * 64;
    const float* Ab = (s < 8) ? g_vbuf + (size_t)s * NEDGES * 320 : g_x2buf;
    const float* Bm = (s < 3) ? g_Wg1 : (s < 8 ? g_Wg2 : g_W1r);
    int lane = tid & 31, warp = tid >> 5;
    int wm = warp & 3, wn = warp >> 2;
    int g = lane >> 2, tig = lane & 3;

    unsigned asA0 = (unsigned)__cvta_generic_to_shared(&As[0][0]);
    unsigned asA1 = (unsigned)__cvta_generic_to_shared(&As[1][0]);
    unsigned asB0 = (unsigned)__cvta_generic_to_shared(&Bs[0][0]);
    unsigned asB1 = (unsigned)__cvta_generic_to_shared(&Bs[1][0]);

    float acc[4][4];
#pragma unroll
    for (int b = 0; b < 4; b++)
#pragma unroll
        for (int c = 0; c < 4; c++) acc[b][c] = 0.f;

    // prologue
    {
#pragma unroll
        for (int i = 0; i < 2; i++) {
            int idx = tid + i * 256;
            int row = idx >> 3, c4 = idx & 7;
            cp16(asA0 + (row * 36 + c4 * 4) * 4, Ab + (size_t)(e0 + row) * 320 + c4 * 4);
        }
#pragma unroll
        for (int i = 0; i < 2; i++) {
            int idx = tid + i * 256;
            int k = idx >> 4, n4 = idx & 15;
            cp16(asB0 + (k * 72 + n4 * 4) * 4, Bm + (size_t)k * 64 + n4 * 4);
        }
        asm volatile("cp.async.commit_group;\n");
    }

    for (int kc = 0; kc < 10; kc++) {
        int buf = kc & 1;
        __syncthreads();
        if (kc < 9) {
            int k0 = (kc + 1) * 32;
            unsigned dA = (buf == 0) ? asA1 : asA0;
            unsigned dB = (buf == 0) ? asB1 : asB0;
#pragma unroll
            for (int i = 0; i < 2; i++) {
                int idx = tid + i * 256;
                int row = idx >> 3, c4 = idx & 7;
                cp16(dA + (row * 36 + c4 * 4) * 4, Ab + (size_t)(e0 + row) * 320 + k0 + c4 * 4);
            }
#pragma unroll
            for (int i = 0; i < 2; i++) {
                int idx = tid + i * 256;
                int k = idx >> 4, n4 = idx & 15;
                cp16(dB + (k * 72 + n4 * 4) * 4, Bm + (size_t)(k0 + k) * 64 + n4 * 4);
            }
            asm volatile("cp.async.commit_group;\n");
            asm volatile("cp.async.wait_group 1;\n");
        } else {
            asm volatile("cp.async.wait_group 0;\n");
        }
        __syncthreads();
        const float* Ac = As[buf];
        const float* Bc = Bs[buf];
#pragma unroll
        for (int ks = 0; ks < 4; ks++) {
            int kb = ks * 8;
            unsigned af[4], bf[4][2];
            int r = wm * 16 + g;
            af[0] = __float_as_uint(Ac[r * 36 + kb + tig]);
            af[1] = __float_as_uint(Ac[(r + 8) * 36 + kb + tig]);
            af[2] = __float_as_uint(Ac[r * 36 + kb + tig + 4]);
            af[3] = __float_as_uint(Ac[(r + 8) * 36 + kb + tig + 4]);
#pragma unroll
            for (int tn = 0; tn < 4; tn++) {
                int c = wn * 32 + tn * 8 + g;
                bf[tn][0] = __float_as_uint(Bc[(kb + tig) * 72 + c]);
                bf[tn][1] = __float_as_uint(Bc[(kb + tig + 4) * 72 + c]);
            }
#pragma unroll
            for (int tn = 0; tn < 4; tn++) {
                asm volatile(
                    "mma.sync.aligned.m16n8k8.row.col.f32.tf32.tf32.f32 "
                    "{%0,%1,%2,%3}, {%4,%5,%6,%7}, {%8,%9}, {%0,%1,%2,%3};\n"
                    : "+f"(acc[tn][0]), "+f"(acc[tn][1]), "+f"(acc[tn][2]), "+f"(acc[tn][3])
                    : "r"(af[0]), "r"(af[1]), "r"(af[2]), "r"(af[3]),
                      "r"(bf[tn][0]), "r"(bf[tn][1]));
            }
        }
    }

    const float scale = 0.05590169943749474f; // 1/sqrt(320)
    float silu_c = g_silu_c;
#pragma unroll
    for (int tn = 0; tn < 4; tn++)
#pragma unroll
        for (int q = 0; q < 4; q++) {
            int r = wm * 16 + g + ((q >= 2) ? 8 : 0);
            int u = wn * 32 + tn * 8 + 2 * tig + (q & 1);
            int e = e0 + r;
            float v = acc[tn][q] * scale;
            if (s < 3) Vout[(size_t)e * 576 + 64 + u * 3 + s] = v;
            else if (s < 8) Vout[(size_t)e * 576 + 256 + u * 5 + (s - 3)] = v;
            else g_h1[(size_t)e * 64 + u] = silu_c * v / (1.f + __expf(-v));
        }
}

// ---------------------------------------------------------------------------
// K3: MLP layers 2+3, envelope, xout, zero Vout scalar block
// ---------------------------------------------------------------------------
__global__ void __launch_bounds__(256) k3_mlp(const float* __restrict__ vectors,
                                              const float* __restrict__ W2,
                                              const float* __restrict__ W3,
                                              float* __restrict__ xout,
                                              float* __restrict__ Vout) {
    __shared__ float h1s[4][64], h2s[4][64];
    int tid = threadIdx.x, sub = tid >> 6, u = tid & 63;
    int e = blockIdx.x * 4 + sub;
    h1s[sub][u] = g_h1[(size_t)e * 64 + u];
    float silu_c = g_silu_c;
    __syncthreads();
    float acc = 0.f;
#pragma unroll 8
    for (int k = 0; k < 64; k++) acc += h1s[sub][k] * W2[k * 64 + u];
    float z = acc * 0.125f;
    h2s[sub][u] = silu_c * z / (1.f + __expf(-z));
    __syncthreads();
    acc = 0.f;
#pragma unroll 8
    for (int k = 0; k < 64; k++) acc += h2s[sub][k] * W3[k * 64 + u];
    float vx = vectors[3 * e], vy = vectors[3 * e + 1], vz = vectors[3 * e + 2];
    float d = sqrtf(vx * vx + vy * vy + vz * vz);
    float d3 = d * d * d, d6 = d3 * d3;
    float env = (d < 1.f) ? 1.f + d6 * (-28.f + d * (48.f - 21.f * d)) : 0.f;
    xout[(size_t)e * 64 + u] = env * acc * 0.125f;
    Vout[(size_t)e * 576 + u] = 0.f;
}

// ---------------------------------------------------------------------------
extern "C" void kernel_launch(void* const* d_in, const int* in_sizes, int n_in,
                              void* d_out, int out_size) {
    const float* vectors = (const float*)d_in[0];
    const float* x       = (const float*)d_in[1];
    const float* V       = (const float*)d_in[2];
    const int*   senders = (const int*)d_in[3];
    const float* W0      = (const float*)d_in[4];
    const float* W1      = (const float*)d_in[5];
    const float* W2      = (const float*)d_in[6];
    const float* W3      = (const float*)d_in[7];
    const float* Wl1     = (const float*)d_in[8];
    const float* Wl2     = (const float*)d_in[9];
    float* xout = (float*)d_out;
    float* Vout = xout + (size_t)NEDGES * 64;

    init_prep_kernel<<<2321, 256>>>(W0, W1, Wl1, Wl2);
    k1_scatter<<<2048, 256>>>(vectors, x, senders);
    k2a_tp<<<8192, 256>>>(V, senders);
    dim3 gg(512, 9);
    k_gemm<<<gg, 256>>>(Vout);
    k3_mlp<<<8192, 256>>>(vectors, W2, W3, xout, Vout);
}

// round 11
// speedup vs baseline: 2.2688x; 1.2305x over previous
#include <cuda_runtime.h>
#include <cuda_fp16.h>
#include <math.h>

#define NNODES 2048
#define NEDGES 32768

// ===========================================================================
// Compile-time e3nn real-basis Wigner 3j machinery
// ===========================================================================
__host__ __device__ constexpr double cfact(int n) {
    double r = 1.0;
    for (int i = 2; i <= n; i++) r *= (double)i;
    return r;
}
__host__ __device__ constexpr double csqrt(double x) {
    if (x <= 0.0) return 0.0;
    double g = x < 1.0 ? 1.0 : x;
    for (int i = 0; i < 80; i++) g = 0.5 * (g + x / g);
    return g;
}
struct CD { double re; double im; };
__host__ __device__ constexpr CD cmul(CD a, CD b) {
    return {a.re * b.re - a.im * b.im, a.re * b.im + a.im * b.re};
}

__host__ __device__ constexpr double su2cg(int j1, int m1, int j2, int m2, int j3, int m3) {
    if (m1 + m2 != m3) return 0.0;
    int vmin = -j1 + j2 + m3;
    if (-j1 + m1 > vmin) vmin = -j1 + m1;
    if (0 > vmin) vmin = 0;
    int vmax = j2 + j3 + m1;
    if (j3 - j1 + j2 < vmax) vmax = j3 - j1 + j2;
    if (j3 + m3 < vmax) vmax = j3 + m3;
    double c = csqrt((2.0 * j3 + 1.0) * cfact(j3 + j1 - j2) * cfact(j3 - j1 + j2) *
                     cfact(j1 + j2 - j3) / cfact(j1 + j2 + j3 + 1) *
                     cfact(j3 + m3) * cfact(j3 - m3) /
                     (cfact(j1 + m1) * cfact(j1 - m1) * cfact(j2 + m2) * cfact(j2 - m2)));
    double s = 0.0;
    for (int v = vmin; v <= vmax; v++) {
        double t = cfact(j2 + j3 + m1 - v) * cfact(j1 - m1 + v) /
                   (cfact(v) * cfact(j3 - j1 + j2 - v) * cfact(j3 + m3 - v) *
                    cfact(v + j1 - j2 - m3));
        s += ((v + j2 + m2) & 1) ? -t : t;
    }
    return c * s;
}

template <int L> struct QM { CD q[(2 * L + 1) * (2 * L + 1)]{}; };

template <int L> __host__ __device__ constexpr QM<L> buildq() {
    QM<L> Q{};
    constexpr int d = 2 * L + 1;
    const double r = csqrt(0.5);
    for (int m = -L; m < 0; m++) {
        Q.q[(L + m) * d + (L - m)] = {r, 0.0};
        Q.q[(L + m) * d + (L + m)] = {0.0, -r};
    }
    Q.q[L * d + L] = {1.0, 0.0};
    for (int m = 1; m <= L; m++) {
        double sg = (m & 1) ? -1.0 : 1.0;
        Q.q[(L + m) * d + (L + m)] = {sg * r, 0.0};
        Q.q[(L + m) * d + (L - m)] = {0.0, sg * r};
    }
    CD ph = (L % 4 == 0) ? CD{1.0, 0.0}
          : (L % 4 == 1) ? CD{0.0, -1.0}
          : (L % 4 == 2) ? CD{-1.0, 0.0}
                         : CD{0.0, 1.0};
    for (int i = 0; i < d * d; i++) Q.q[i] = cmul(Q.q[i], ph);
    return Q;
}

template <int L1, int L2, int L3> struct W3J {
    float c[(2 * L1 + 1) * (2 * L2 + 1) * (2 * L3 + 1)]{};
};

template <int L1, int L2, int L3> __host__ __device__ constexpr W3J<L1, L2, L3> w3j() {
    constexpr int d1 = 2 * L1 + 1, d2 = 2 * L2 + 1, d3 = 2 * L3 + 1;
    double C[d1 * d2 * d3]{};
    for (int m1 = -L1; m1 <= L1; m1++)
        for (int m2 = -L2; m2 <= L2; m2++) {
            int m3 = m1 + m2;
            if (m3 >= -L3 && m3 <= L3)
                C[((L1 + m1) * d2 + (L2 + m2)) * d3 + (L3 + m3)] = su2cg(L1, m1, L2, m2, L3, m3);
        }
    QM<L1> q1 = buildq<L1>();
    QM<L2> q2 = buildq<L2>();
    QM<L3> q3 = buildq<L3>();
    double out[d1 * d2 * d3]{};
    double ss = 0.0;
    for (int j = 0; j < d1; j++)
        for (int l = 0; l < d2; l++)
            for (int n = 0; n < d3; n++) {
                double re = 0.0;
                for (int i = 0; i < d1; i++)
                    for (int k = 0; k < d2; k++) {
                        CD ab = cmul(q1.q[i * d1 + j], q2.q[k * d2 + l]);
                        for (int m = 0; m < d3; m++) {
                            double cv = C[(i * d2 + k) * d3 + m];
                            if (cv != 0.0) {
                                CD g = q3.q[m * d3 + n];
                                re += cv * (ab.re * g.re + ab.im * g.im); // conj(g)
                            }
                        }
                    }
                out[(j * d2 + l) * d3 + n] = re;
                ss += re * re;
            }
    double inv = 1.0 / csqrt(ss);
    W3J<L1, L2, L3> R{};
    for (int idx = 0; idx < d1 * d2 * d3; idx++) R.c[idx] = (float)(out[idx] * inv);
    return R;
}

template <int L1, int L2, int L3> struct CGH {
    static constexpr W3J<L1, L2, L3> v = w3j<L1, L2, L3>();
};

__host__ __device__ constexpr bool rowAnyF(const float* c, int d2, int d3, int I, int J) {
    for (int k = 0; k < d3; k++)
        if (c[(I * d2 + J) * d3 + k] != 0.f) return true;
    return false;
}
template <int L1, int L2, int L3, int I, int J> struct RowAny {
    static constexpr bool value =
        rowAnyF(CGH<L1, L2, L3>::v.c, 2 * L2 + 1, 2 * L3 + 1, I, J);
};

// template-recursive TP with immediate constants, zero terms skipped
template <int L1, int L2, int L3, int I, int J, int K>
__device__ __forceinline__ void tp_k(float t, float* dst) {
    if constexpr (K < 2 * L3 + 1) {
        constexpr float cv = CGH<L1, L2, L3>::v.c[(I * (2 * L2 + 1) + J) * (2 * L3 + 1) + K];
        if constexpr (cv != 0.f) dst[K] += t * cv;
        tp_k<L1, L2, L3, I, J, K + 1>(t, dst);
    }
}
template <int L1, int L2, int L3, int I, int J>
__device__ __forceinline__ void tp_ij(const float* wr, const float* vr, float* dst) {
    if constexpr (J < 2 * L2 + 1) {
        if constexpr (RowAny<L1, L2, L3, I, J>::value) {
            float t = wr[L1 * L1 + I] * vr[L2 * L2 + J];
            tp_k<L1, L2, L3, I, J, 0>(t, dst);
        }
        tp_ij<L1, L2, L3, I, J + 1>(wr, vr, dst);
    }
}
template <int L1, int L2, int L3, int I>
__device__ __forceinline__ void tp_i(const float* wr, const float* vr, float* dst) {
    if constexpr (I < 2 * L1 + 1) {
        tp_ij<L1, L2, L3, I, 0>(wr, vr, dst);
        tp_i<L1, L2, L3, I + 1>(wr, vr, dst);
    }
}
template <int L1, int L2, int L3>
__device__ __forceinline__ void tp_full(const float* wr, const float* vr, float* dst) {
#pragma unroll
    for (int k = 0; k < 2 * L3 + 1; k++) dst[k] = 0.f;
    tp_i<L1, L2, L3, 0>(wr, vr, dst);
}

// SH recursion scales
__host__ __device__ constexpr double sh_scale(int which) {
    double n0 = 0.3, n1 = 0.5, n2 = 0.81;
    double inv = 1.0 / csqrt(n0 * n0 + n1 * n1 + n2 * n2);
    double ny[3] = {n1 * inv, n2 * inv, n0 * inv};
    constexpr W3J<1, 1, 2> cg112 = w3j<1, 1, 2>();
    constexpr W3J<2, 1, 3> cg213 = w3j<2, 1, 3>();
    double Y1[3] = {0, 0, 0};
    for (int i = 0; i < 3; i++) Y1[i] = csqrt(3.0) * ny[i];
    double A[5] = {0, 0, 0, 0, 0};
    for (int i = 0; i < 3; i++)
        for (int j = 0; j < 3; j++) {
            double t = Y1[i] * ny[j];
            for (int k = 0; k < 5; k++) A[k] += t * (double)cg112.c[(i * 3 + j) * 5 + k];
        }
    double na = 0;
    for (int k = 0; k < 5; k++) na += A[k] * A[k];
    double s0 = csqrt(5.0) / csqrt(na);
    if (which == 0) return s0;
    double Y2[5] = {0, 0, 0, 0, 0};
    for (int k = 0; k < 5; k++) Y2[k] = A[k] * s0;
    double B[7] = {0, 0, 0, 0, 0, 0, 0};
    for (int i = 0; i < 5; i++)
        for (int j = 0; j < 3; j++) {
            double t = Y2[i] * ny[j];
            for (int k = 0; k < 7; k++) B[k] += t * (double)cg213.c[(i * 3 + j) * 7 + k];
        }
    double nb = 0;
    for (int k = 0; k < 7; k++) nb += B[k] * B[k];
    return csqrt(7.0) / csqrt(nb);
}
constexpr float SH_S0 = (float)sh_scale(0);
constexpr float SH_S1 = (float)sh_scale(1);

// ===========================================================================
__device__ float g_silu_c;
__device__ __align__(16) float g_node_sum[NNODES * 1024];
__device__ __align__(16) float g_W0T[8192];
__device__ __align__(16) __half g_W1h[20480];   // [n=64][k=320]
__device__ __align__(16) __half g_Wg1h[20480];  // [u=64][mp=320]
__device__ __align__(16) __half g_Wg2h[20480];
__device__ __align__(16) __half g_vbufh[(size_t)8 * NEDGES * 320];
__device__ __align__(16) __half g_x2h[(size_t)NEDGES * 320];
__device__ __align__(16) float g_h1[(size_t)NEDGES * 64];

__device__ __forceinline__ void cp16(unsigned dst, const void* src) {
    asm volatile("cp.async.cg.shared.global [%0], [%1], 16;\n" :: "r"(dst), "l"(src));
}

// ---------------------------------------------------------------------------
// init: block 0 = silu_c; [1,273) = weight prep; [273,2321) = zero node_sum
// ---------------------------------------------------------------------------
__global__ void init_prep_kernel(const float* __restrict__ W0, const float* __restrict__ W1,
                                 const float* __restrict__ Wl1, const float* __restrict__ Wl2) {
    __shared__ float red[256];
    int tid = threadIdx.x, b = blockIdx.x;
    if (b == 0) {
        float part = 0.f;
        for (int i = tid; i < 20001; i += blockDim.x) {
            float z = -12.f + 24.f * (float)i / 20000.f;
            float s = z / (1.f + expf(-z));
            float phi = expf(-0.5f * z * z) * 0.3989422804014327f;
            float w = (i == 0 || i == 20000) ? 0.5f : 1.f;
            part += w * s * s * phi;
        }
        red[tid] = part;
        __syncthreads();
        for (int st = 128; st > 0; st >>= 1) {
            if (tid < st) red[tid] += red[tid + st];
            __syncthreads();
        }
        if (tid == 0) g_silu_c = rsqrtf(red[0] * (24.f / 20000.f));
    } else if (b < 273) {
        int i = (b - 1) * 256 + tid;
        if (i < 8192) {
            int k4 = i >> 8, rm = i & 255, u = rm >> 2, r = rm & 3;
            g_W0T[i] = W0[(k4 * 4 + r) * 64 + u];
            return;
        }
        i -= 8192;
        if (i < 20480) {  // W1h[n][k] = W1[k*64+n]
            int n = i / 320, k = i % 320;
            g_W1h[i] = __float2half_rn(W1[k * 64 + n]);
            return;
        }
        i -= 20480;
        if (i < 20480) {  // Wg1h[u][mp], mp = p*64+um
            int u = i / 320, mp = i % 320, p = mp >> 6, um = mp & 63;
            g_Wg1h[i] = __float2half_rn(Wl1[(um * 5 + p) * 64 + u]);
            return;
        }
        i -= 20480;
        if (i < 20480) {
            int u = i / 320, mp = i % 320, p = mp >> 6, um = mp & 63;
            g_Wg2h[i] = __float2half_rn(Wl2[(um * 5 + p) * 64 + u]);
        }
    } else {
        int i = (b - 273) * 256 + tid;
        ((float4*)g_node_sum)[i] = make_float4(0.f, 0.f, 0.f, 0.f);
    }
}

// ---------------------------------------------------------------------------
// K1: w = x@W0/sqrt(128), SH via constexpr recursion, scatter, x->x2h
// ---------------------------------------------------------------------------
__global__ void __launch_bounds__(256) k1_scatter(const float* __restrict__ vectors,
                                                  const float* __restrict__ x,
                                                  const int* __restrict__ senders) {
    __shared__ __align__(16) float xs[16][128];
    __shared__ float ws[16][64];
    __shared__ float Ys[16][16];
    __shared__ int sends[16];
    int tid = threadIdx.x;
    int eb = blockIdx.x * 16;
    if (tid < 16) sends[tid] = senders[eb + tid];
#pragma unroll
    for (int r = 0; r < 2; r++) {
        int idx = tid + r * 256;
        int e = idx >> 5, q = idx & 31;
        float4 v = ((const float4*)(x + (size_t)(eb + e) * 128))[q];
        *(float4*)&xs[e][q * 4] = v;
        __half2 h0 = __floats2half2_rn(v.x, v.y);
        __half2 h1 = __floats2half2_rn(v.z, v.w);
        *(__half2*)(g_x2h + (size_t)(eb + e) * 320 + q * 4) = h0;
        *(__half2*)(g_x2h + (size_t)(eb + e) * 320 + q * 4 + 2) = h1;
    }
    __syncthreads();
    int g = tid >> 6, u = tid & 63;
    float acc[4] = {0, 0, 0, 0};
#pragma unroll
    for (int k4 = 0; k4 < 32; k4++) {
        float4 w = *(const float4*)&g_W0T[k4 * 256 + u * 4];
#pragma unroll
        for (int c = 0; c < 4; c++) {
            float4 xv = *(const float4*)&xs[g * 4 + c][k4 * 4];
            acc[c] += w.x * xv.x + w.y * xv.y + w.z * xv.z + w.w * xv.w;
        }
    }
#pragma unroll
    for (int c = 0; c < 4; c++) ws[g * 4 + c][u] = acc[c] * 0.08838834764831845f;
    if (tid < 16) {
        int e = eb + tid;
        float vx = vectors[3 * e], vy = vectors[3 * e + 1], vz = vectors[3 * e + 2];
        float inv = rsqrtf(vx * vx + vy * vy + vz * vz);
        float nb4[4] = {0.f, vy * inv, vz * inv, vx * inv};
        Ys[tid][0] = 1.f;
        float wb[4];
        wb[0] = 0.f;
#pragma unroll
        for (int i = 0; i < 3; i++) {
            wb[1 + i] = 1.7320508075688772f * nb4[1 + i];
            Ys[tid][1 + i] = wb[1 + i];
        }
        float Y2[5];
        tp_full<1, 1, 2>(wb, nb4, Y2);
        float wb2[9] = {0, 0, 0, 0, 0, 0, 0, 0, 0};
#pragma unroll
        for (int k = 0; k < 5; k++) {
            Y2[k] *= SH_S0;
            Ys[tid][4 + k] = Y2[k];
            wb2[4 + k] = Y2[k];
        }
        float Y3[7];
        tp_full<2, 1, 3>(wb2, nb4, Y3);
#pragma unroll
        for (int k = 0; k < 7; k++) Ys[tid][9 + k] = Y3[k] * SH_S1;
    }
    __syncthreads();
#pragma unroll
    for (int it = 0; it < 16; it++) {
        int t = tid + it * 256;
        int e = t >> 8, q = t & 255;
        int uu = q >> 2, i0 = (q & 3) * 4;
        float w = ws[e][uu];
        atomicAdd((float4*)(g_node_sum + (size_t)sends[e] * 1024 + q * 4),
                  make_float4(w * Ys[e][i0], w * Ys[e][i0 + 1], w * Ys[e][i0 + 2], w * Ys[e][i0 + 3]));
    }
}

// ---------------------------------------------------------------------------
// K2a: tensor product per edge, constexpr CG, fp16 outputs
// ---------------------------------------------------------------------------
__global__ void __launch_bounds__(256, 3) k2a_tp(const float* __restrict__ V,
                                                 const int* __restrict__ senders) {
    __shared__ float wYs[4][64 * 17];
    __shared__ __align__(16) float Vs[4][576];
    __shared__ int sends[4];
    int tid = threadIdx.x;
    int eb = blockIdx.x * 4;
    if (tid < 4) sends[tid] = senders[eb + tid];
    __syncthreads();
    for (int t = tid; t < 1024; t += 256) {
        int sub = t >> 8, r = t & 255;
        float4 v = ((const float4*)(g_node_sum + (size_t)sends[sub] * 1024))[r];
        int uu = r >> 2, j0 = (r & 3) * 4;
        float* d = &wYs[sub][uu * 17 + j0];
        d[0] = v.x * 0.25f; d[1] = v.y * 0.25f; d[2] = v.z * 0.25f; d[3] = v.w * 0.25f;
    }
    for (int t = tid; t < 576; t += 256) {
        int sub = t / 144, r = t - sub * 144;
        ((float4*)Vs[sub])[r] = ((const float4*)(V + (size_t)(eb + sub) * 576))[r];
    }
    __syncthreads();
    int sub = tid >> 6, u = tid & 63;
    int e = eb + sub;
    float wr[16], vr[9];
#pragma unroll
    for (int j = 0; j < 16; j++) wr[j] = wYs[sub][u * 17 + j];
#pragma unroll
    for (int j = 0; j < 9; j++) vr[j] = Vs[sub][u * 9 + j];

    const float R3 = 1.7320508075688772f, R5 = 2.2360679774997896f;
    // scalars
    {
        float s0o[3], t1[1];
        tp_full<0, 0, 0>(wr, vr, t1); s0o[0] = t1[0];
        tp_full<1, 1, 0>(wr, vr, t1); s0o[1] = t1[0];
        tp_full<2, 2, 0>(wr, vr, t1); s0o[2] = t1[0];
        __half* x2p = g_x2h + (size_t)e * 320 + 128 + u * 3;
        x2p[0] = __float2half_rn(s0o[0]);
        x2p[1] = __float2half_rn(s0o[1]);
        x2p[2] = __float2half_rn(s0o[2]);
    }
    // l=1 outputs
    {
        float o1[5][3];
        tp_full<0, 1, 1>(wr, vr, o1[0]);
        tp_full<1, 0, 1>(wr, vr, o1[1]);
        tp_full<1, 2, 1>(wr, vr, o1[2]);
        tp_full<2, 1, 1>(wr, vr, o1[3]);
        tp_full<3, 2, 1>(wr, vr, o1[4]);
#pragma unroll
        for (int i = 0; i < 3; i++)
#pragma unroll
            for (int p = 0; p < 5; p++)
                g_vbufh[((size_t)i * NEDGES + e) * 320 + p * 64 + u] = __float2half_rn(R3 * o1[p][i]);
    }
    // l=2 outputs
    {
        float o2[5][5];
        tp_full<0, 2, 2>(wr, vr, o2[0]);
        tp_full<1, 1, 2>(wr, vr, o2[1]);
        tp_full<2, 0, 2>(wr, vr, o2[2]);
        tp_full<2, 2, 2>(wr, vr, o2[3]);
        tp_full<3, 1, 2>(wr, vr, o2[4]);
#pragma unroll
        for (int i = 0; i < 5; i++)
#pragma unroll
            for (int p = 0; p < 5; p++)
                g_vbufh[((size_t)(3 + i) * NEDGES + e) * 320 + p * 64 + u] = __float2half_rn(R5 * o2[p][i]);
    }
}

// ---------------------------------------------------------------------------
// K_gemm: 9 slices of [32768x320]@[320x64], fp16 m16n8k16, M-tile 128
// As: [128][40] halves, Bs: [64][40] halves (B stored [n][k])
// ---------------------------------------------------------------------------
__global__ void __launch_bounds__(256, 4) k_gemm(float* __restrict__ Vout) {
    __shared__ __align__(16) __half As[2][128 * 40];
    __shared__ __align__(16) __half Bs[2][64 * 40];
    int tid = threadIdx.x, s = blockIdx.y;
    int e0 = blockIdx.x * 128;
    const __half* Ab = (s < 8) ? g_vbufh + (size_t)s * NEDGES * 320 : g_x2h;
    const __half* Bm = (s < 3) ? g_Wg1h : (s < 8 ? g_Wg2h : g_W1h);
    int lane = tid & 31, warp = tid >> 5;
    int wm = warp & 3, wn = warp >> 2;
    int g = lane >> 2, tig = lane & 3;

    unsigned asA0 = (unsigned)__cvta_generic_to_shared(&As[0][0]);
    unsigned asA1 = (unsigned)__cvta_generic_to_shared(&As[1][0]);
    unsigned asB0 = (unsigned)__cvta_generic_to_shared(&Bs[0][0]);
    unsigned asB1 = (unsigned)__cvta_generic_to_shared(&Bs[1][0]);

    float acc[2][4][4];
#pragma unroll
    for (int a = 0; a < 2; a++)
#pragma unroll
        for (int b = 0; b < 4; b++)
#pragma unroll
            for (int c = 0; c < 4; c++) acc[a][b][c] = 0.f;

    // prologue: chunk 0 (A: 512 cp16, B: 256 cp16)
    {
#pragma unroll
        for (int i = 0; i < 2; i++) {
            int idx = tid + i * 256;
            int row = idx >> 2, c8 = idx & 3;
            cp16(asA0 + (row * 40 + c8 * 8) * 2, Ab + (size_t)(e0 + row) * 320 + c8 * 8);
        }
        {
            int n = tid >> 2, c8 = tid & 3;
            cp16(asB0 + (n * 40 + c8 * 8) * 2, Bm + (size_t)n * 320 + c8 * 8);
        }
        asm volatile("cp.async.commit_group;\n");
    }

    for (int kc = 0; kc < 10; kc++) {
        int buf = kc & 1;
        __syncthreads();
        if (kc < 9) {
            int k0 = (kc + 1) * 32;
            unsigned dA = (buf == 0) ? asA1 : asA0;
            unsigned dB = (buf == 0) ? asB1 : asB0;
#pragma unroll
            for (int i = 0; i < 2; i++) {
                int idx = tid + i * 256;
                int row = idx >> 2, c8 = idx & 3;
                cp16(dA + (row * 40 + c8 * 8) * 2, Ab + (size_t)(e0 + row) * 320 + k0 + c8 * 8);
            }
            {
                int n = tid >> 2, c8 = tid & 3;
                cp16(dB + (n * 40 + c8 * 8) * 2, Bm + (size_t)n * 320 + k0 + c8 * 8);
            }
            asm volatile("cp.async.commit_group;\n");
            asm volatile("cp.async.wait_group 1;\n");
        } else {
            asm volatile("cp.async.wait_group 0;\n");
        }
        __syncthreads();
        const __half* Ac = As[buf];
        const __half* Bc = Bs[buf];
#pragma unroll
        for (int ks = 0; ks < 2; ks++) {
            int kb = ks * 16;
            unsigned af[2][4], bf[4][2];
#pragma unroll
            for (int tm = 0; tm < 2; tm++) {
                int r = wm * 32 + tm * 16 + g;
                af[tm][0] = *(const unsigned*)&Ac[r * 40 + kb + 2 * tig];
                af[tm][1] = *(const unsigned*)&Ac[(r + 8) * 40 + kb + 2 * tig];
                af[tm][2] = *(const unsigned*)&Ac[r * 40 + kb + 2 * tig + 8];
                af[tm][3] = *(const unsigned*)&Ac[(r + 8) * 40 + kb + 2 * tig + 8];
            }
#pragma unroll
            for (int tn = 0; tn < 4; tn++) {
                int c = wn * 32 + tn * 8 + g;
                bf[tn][0] = *(const unsigned*)&Bc[c * 40 + kb + 2 * tig];
                bf[tn][1] = *(const unsigned*)&Bc[c * 40 + kb + 2 * tig + 8];
            }
#pragma unroll
            for (int tm = 0; tm < 2; tm++)
#pragma unroll
                for (int tn = 0; tn < 4; tn++) {
                    asm volatile(
                        "mma.sync.aligned.m16n8k16.row.col.f32.f16.f16.f32 "
                        "{%0,%1,%2,%3}, {%4,%5,%6,%7}, {%8,%9}, {%0,%1,%2,%3};\n"
                        : "+f"(acc[tm][tn][0]), "+f"(acc[tm][tn][1]),
                          "+f"(acc[tm][tn][2]), "+f"(acc[tm][tn][3])
                        : "r"(af[tm][0]), "r"(af[tm][1]), "r"(af[tm][2]), "r"(af[tm][3]),
                          "r"(bf[tn][0]), "r"(bf[tn][1]));
                }
        }
    }

    const float scale = 0.05590169943749474f; // 1/sqrt(320)
    float silu_c = g_silu_c;
#pragma unroll
    for (int tm = 0; tm < 2; tm++)
#pragma unroll
        for (int tn = 0; tn < 4; tn++)
#pragma unroll
            for (int q = 0; q < 4; q++) {
                int r = wm * 32 + tm * 16 + g + ((q >= 2) ? 8 : 0);
                int u = wn * 32 + tn * 8 + 2 * tig + (q & 1);
                int e = e0 + r;
                float v = acc[tm][tn][q] * scale;
                if (s < 3) Vout[(size_t)e * 576 + 64 + u * 3 + s] = v;
                else if (s < 8) Vout[(size_t)e * 576 + 256 + u * 5 + (s - 3)] = v;
                else g_h1[(size_t)e * 64 + u] = silu_c * v / (1.f + __expf(-v));
            }
}

// ---------------------------------------------------------------------------
// K3: MLP layers 2+3, envelope, xout, zero Vout scalar block
// ---------------------------------------------------------------------------
__global__ void __launch_bounds__(256) k3_mlp(const float* __restrict__ vectors,
                                              const float* __restrict__ W2,
                                              const float* __restrict__ W3,
                                              float* __restrict__ xout,
                                              float* __restrict__ Vout) {
    __shared__ float h1s[4][64], h2s[4][64];
    int tid = threadIdx.x, sub = tid >> 6, u = tid & 63;
    int e = blockIdx.x * 4 + sub;
    h1s[sub][u] = g_h1[(size_t)e * 64 + u];
    float silu_c = g_silu_c;
    __syncthreads();
    float acc = 0.f;
#pragma unroll 8
    for (int k = 0; k < 64; k++) acc += h1s[sub][k] * W2[k * 64 + u];
    float z = acc * 0.125f;
    h2s[sub][u] = silu_c * z / (1.f + __expf(-z));
    __syncthreads();
    acc = 0.f;
#pragma unroll 8
    for (int k = 0; k < 64; k++) acc += h2s[sub][k] * W3[k * 64 + u];
    float vx = vectors[3 * e], vy = vectors[3 * e + 1], vz = vectors[3 * e + 2];
    float d = sqrtf(vx * vx + vy * vy + vz * vz);
    float d3 = d * d * d, d6 = d3 * d3;
    float env = (d < 1.f) ? 1.f + d6 * (-28.f + d * (48.f - 21.f * d)) : 0.f;
    xout[(size_t)e * 64 + u] = env * acc * 0.125f;
    Vout[(size_t)e * 576 + u] = 0.f;
}

// ---------------------------------------------------------------------------
extern "C" void kernel_launch(void* const* d_in, const int* in_sizes, int n_in,
                              void* d_out, int out_size) {
    const float* vectors = (const float*)d_in[0];
    const float* x       = (const float*)d_in[1];
    const float* V       = (const float*)d_in[2];
    const int*   senders = (const int*)d_in[3];
    const float* W0      = (const float*)d_in[4];
    const float* W1      = (const float*)d_in[5];
    const float* W2      = (const float*)d_in[6];
    const float* W3      = (const float*)d_in[7];
    const float* Wl1     = (const float*)d_in[8];
    const float* Wl2     = (const float*)d_in[9];
    float* xout = (float*)d_out;
    float* Vout = xout + (size_t)NEDGES * 64;

    init_prep_kernel<<<2321, 256>>>(W0, W1, Wl1, Wl2);
    k1_scatter<<<2048, 256>>>(vectors, x, senders);
    k2a_tp<<<8192, 256>>>(V, senders);
    dim3 gg(256, 9);
    k_gemm<<<gg, 256>>>(Vout);
    k3_mlp<<<8192, 256>>>(vectors, W2, W3, xout, Vout);
}